// round 2
// baseline (speedup 1.0000x reference)
#include <cuda_runtime.h>
#include <math.h>
#include <stdint.h>

#define NN 100000
#define NE 1600000
#define HID 128
#define OUTF 64

// ---------------- scratch (static device globals; no allocations) ----------
__device__ __align__(16) float g_deg[NN];
__device__ __align__(16) float g_rdeg[NN];
__device__ int   g_src[NE];
__device__ int   g_dst[NE];
__device__ __align__(16) float g_agg[NN * HID];
__device__ __align__(16) float g_hA[NN * HID];
__device__ __align__(16) float g_hB[NN * HID];
__device__ __align__(16) float g_bn[4][HID];   // [0]=sum [1]=sumsq [2]=scale [3]=shift
__device__ int   g_idx64;

// ---------------- helpers --------------------------------------------------
__device__ __forceinline__ void red_add_v4(float* gptr, float4 v) {
    asm volatile("red.global.add.v4.f32 [%0], {%1, %2, %3, %4};"
                 :: "l"(gptr), "f"(v.x), "f"(v.y), "f"(v.z), "f"(v.w)
                 : "memory");
}

// ---------------- index width detection + conversion -----------------------
__global__ void detect_kernel(const unsigned int* p) {
    // If src is int64 (values < 2^31), every high 32-bit word is 0.
    int ok = 1;
    for (int i = 1; i < 128; i += 2)
        if (p[i] != 0u) ok = 0;
    g_idx64 = ok;
}

__global__ void convert_kernel(const void* srcv, const void* dstv) {
    int e = blockIdx.x * blockDim.x + threadIdx.x;
    if (e >= NE) return;
    if (g_idx64) {
        g_src[e] = (int)((const long long*)srcv)[e];
        g_dst[e] = (int)((const long long*)dstv)[e];
    } else {
        g_src[e] = ((const int*)srcv)[e];
        g_dst[e] = ((const int*)dstv)[e];
    }
}

// ---------------- degree ----------------------------------------------------
__global__ void deg_kernel() {
    int e = blockIdx.x * blockDim.x + threadIdx.x;
    if (e >= NE) return;
    atomicAdd(&g_deg[g_dst[e]], 1.0f);
}

__global__ void rdeg_kernel() {
    int i = blockIdx.x * blockDim.x + threadIdx.x;
    if (i >= NN) return;
    g_rdeg[i] = 1.0f / fmaxf(g_deg[i], 1.0f);
}

// ---------------- edge scatter: agg[dst] += h[src]  (one warp per edge) ----
__global__ __launch_bounds__(256) void scatter_kernel(const float* __restrict__ h) {
    int warp_g = (blockIdx.x * blockDim.x + threadIdx.x) >> 5;
    int lane   = threadIdx.x & 31;
    if (warp_g >= NE) return;
    int s = g_src[warp_g];
    int d = g_dst[warp_g];
    const float4* hp = (const float4*)(h + (size_t)s * HID);
    float4 v = hp[lane];
    red_add_v4(g_agg + (size_t)d * HID + lane * 4, v);
}

// ---------------- fused GEMM: out = [h | agg*rdeg] @ [Wself; Wneigh] + b ----
// MODE 0: write raw linear out + accumulate BN sum/sumsq
// MODE 1: fused log_softmax over COLS(=64) columns
template<int COLS, int MODE>
__global__ __launch_bounds__(256, 2) void sage_gemm(
    const float* __restrict__ hin,
    const float* __restrict__ wself, const float* __restrict__ wneigh,
    const float* __restrict__ bias, float* __restrict__ outp)
{
    constexpr int TN = COLS / 16;
    __shared__ float As[16][132];
    __shared__ float Ws[16][COLS];
    __shared__ float sred[256];

    const int tid = threadIdx.x;
    const int tx = tid & 15;      // col group
    const int ty = tid >> 4;      // row group
    const int row0 = blockIdx.x * 128;

    float acc[8][TN];
#pragma unroll
    for (int i = 0; i < 8; i++)
#pragma unroll
        for (int j = 0; j < TN; j++) acc[i][j] = 0.0f;

    for (int kb = 0; kb < 256; kb += 16) {
        // --- load A tile: As[k][row], 128 rows x 16 k ---
#pragma unroll
        for (int it = 0; it < 2; it++) {
            int cidx = tid + it * 256;       // 0..511 float4 chunks
            int r  = cidx >> 2;              // 0..127
            int k4 = (cidx & 3) * 4;         // 0,4,8,12
            int row = row0 + r;
            int kk = kb + k4;
            float4 v = make_float4(0.f, 0.f, 0.f, 0.f);
            if (row < NN) {
                if (kk < 128) {
                    v = *(const float4*)(hin + (size_t)row * HID + kk);
                } else {
                    v = *(const float4*)(g_agg + (size_t)row * HID + (kk - 128));
                    float sc = g_rdeg[row];
                    v.x *= sc; v.y *= sc; v.z *= sc; v.w *= sc;
                }
            }
            As[k4 + 0][r] = v.x;
            As[k4 + 1][r] = v.y;
            As[k4 + 2][r] = v.z;
            As[k4 + 3][r] = v.w;
        }
        // --- load W tile: Ws[k][c], 16 k x COLS ---
#pragma unroll
        for (int it = 0; it < (16 * COLS / 4) / 256; it++) {
            int cidx = tid + it * 256;
            int k  = cidx / (COLS / 4);
            int c4 = (cidx % (COLS / 4)) * 4;
            int kk = kb + k;
            const float* w = (kk < 128)
                ? (wself  + (size_t)kk * COLS + c4)
                : (wneigh + (size_t)(kk - 128) * COLS + c4);
            *(float4*)&Ws[k][c4] = *(const float4*)w;
        }
        __syncthreads();

#pragma unroll
        for (int k = 0; k < 16; k++) {
            float a[8], b[TN];
            *(float4*)&a[0] = *(const float4*)&As[k][ty * 8];
            *(float4*)&a[4] = *(const float4*)&As[k][ty * 8 + 4];
#pragma unroll
            for (int j = 0; j < TN; j += 4)
                *(float4*)&b[j] = *(const float4*)&Ws[k][tx * TN + j];
#pragma unroll
            for (int i = 0; i < 8; i++)
#pragma unroll
                for (int j = 0; j < TN; j++)
                    acc[i][j] = fmaf(a[i], b[j], acc[i][j]);
        }
        __syncthreads();
    }

    float bfr[TN];
#pragma unroll
    for (int j = 0; j < TN; j++) bfr[j] = bias[tx * TN + j];

    if (MODE == 0) {
        float vsum[TN], vsq[TN];
#pragma unroll
        for (int j = 0; j < TN; j++) { vsum[j] = 0.f; vsq[j] = 0.f; }
#pragma unroll
        for (int i = 0; i < 8; i++) {
            int row = row0 + ty * 8 + i;
            if (row < NN) {
                float o[TN];
#pragma unroll
                for (int j = 0; j < TN; j++) {
                    float v = acc[i][j] + bfr[j];
                    o[j] = v;
                    vsum[j] += v;
                    vsq[j]  += v * v;
                }
#pragma unroll
                for (int j = 0; j < TN; j += 4)
                    *(float4*)(outp + (size_t)row * COLS + tx * TN + j) = *(float4*)&o[j];
            }
        }
        // block-level BN partial reduce, then one global atomic per column
        sred[tid] = 0.0f;
        __syncthreads();
#pragma unroll
        for (int j = 0; j < TN; j++) {
            atomicAdd(&sred[tx * TN + j], vsum[j]);
            atomicAdd(&sred[128 + tx * TN + j], vsq[j]);
        }
        __syncthreads();
        if (tid < 128) {
            atomicAdd(&g_bn[0][tid], sred[tid]);
            atomicAdd(&g_bn[1][tid], sred[128 + tid]);
        }
    } else {
        // fused log_softmax across COLS=64: 16 threads (tx) own 4 cols each;
        // butterfly over low 4 lane bits reduces across tx within the warp.
#pragma unroll
        for (int i = 0; i < 8; i++) {
            int row = row0 + ty * 8 + i;
            float v[TN];
            float m = -INFINITY;
#pragma unroll
            for (int j = 0; j < TN; j++) {
                v[j] = acc[i][j] + bfr[j];
                m = fmaxf(m, v[j]);
            }
#pragma unroll
            for (int off = 8; off > 0; off >>= 1)
                m = fmaxf(m, __shfl_xor_sync(0xffffffffu, m, off));
            float s = 0.0f;
#pragma unroll
            for (int j = 0; j < TN; j++) s += expf(v[j] - m);
#pragma unroll
            for (int off = 8; off > 0; off >>= 1)
                s += __shfl_xor_sync(0xffffffffu, s, off);
            float lse = m + logf(s);
            if (row < NN) {
                float o[TN];
#pragma unroll
                for (int j = 0; j < TN; j++) o[j] = v[j] - lse;
                *(float4*)(outp + (size_t)row * COLS + tx * TN) = *(float4*)&o[0];
            }
        }
    }
}

// ---------------- BN finalize + apply --------------------------------------
__global__ void bn_finalize_kernel(const float* __restrict__ gamma,
                                   const float* __restrict__ beta) {
    int c = threadIdx.x;
    if (c >= HID) return;
    float s  = g_bn[0][c];
    float sq = g_bn[1][c];
    float mu  = s / (float)NN;
    float var = sq / (float)NN - mu * mu;
    float sc = gamma[c] * rsqrtf(var + 1e-5f);
    g_bn[2][c] = sc;
    g_bn[3][c] = beta[c] - mu * sc;
}

__global__ __launch_bounds__(256) void bn_apply_kernel(const float* __restrict__ in,
                                                       float* __restrict__ outp) {
    int idx = blockIdx.x * blockDim.x + threadIdx.x;   // float4 index
    if (idx >= NN * (HID / 4)) return;
    float4 v = ((const float4*)in)[idx];
    int c = (idx & (HID / 4 - 1)) * 4;
    float4 o;
    o.x = fmaxf(fmaf(v.x, g_bn[2][c + 0], g_bn[3][c + 0]), 0.0f);
    o.y = fmaxf(fmaf(v.y, g_bn[2][c + 1], g_bn[3][c + 1]), 0.0f);
    o.z = fmaxf(fmaf(v.z, g_bn[2][c + 2], g_bn[3][c + 2]), 0.0f);
    o.w = fmaxf(fmaf(v.w, g_bn[2][c + 3], g_bn[3][c + 3]), 0.0f);
    ((float4*)outp)[idx] = o;
}

// ---------------- launch ----------------------------------------------------
extern "C" void kernel_launch(void* const* d_in, const int* in_sizes, int n_in,
                              void* d_out, int out_size) {
    const float* x   = (const float*)d_in[0];
    const void*  src = d_in[1];
    const void*  dst = d_in[2];
    const float* ws0 = (const float*)d_in[3];
    const float* wn0 = (const float*)d_in[4];
    const float* b0  = (const float*)d_in[5];
    const float* ws1 = (const float*)d_in[6];
    const float* wn1 = (const float*)d_in[7];
    const float* b1  = (const float*)d_in[8];
    const float* ws2 = (const float*)d_in[9];
    const float* wn2 = (const float*)d_in[10];
    const float* b2  = (const float*)d_in[11];
    const float* gamma0 = (const float*)d_in[12];
    const float* beta0  = (const float*)d_in[13];
    const float* gamma1 = (const float*)d_in[14];
    const float* beta1  = (const float*)d_in[15];
    float* out = (float*)d_out;

    void *aggp, *degp, *bnp, *hAp, *hBp;
    cudaGetSymbolAddress(&aggp, g_agg);
    cudaGetSymbolAddress(&degp, g_deg);
    cudaGetSymbolAddress(&bnp,  g_bn);
    cudaGetSymbolAddress(&hAp,  g_hA);
    cudaGetSymbolAddress(&hBp,  g_hB);
    float* hA = (float*)hAp;
    float* hB = (float*)hBp;

    const int egrid = (NE + 255) / 256;
    const int mgrid = (NN + 127) / 128;          // 782
    const int agrid = (NN * (HID / 4) + 255) / 256;

    detect_kernel<<<1, 1>>>((const unsigned int*)src);
    convert_kernel<<<egrid, 256>>>(src, dst);

    cudaMemsetAsync(degp, 0, NN * sizeof(float));
    deg_kernel<<<egrid, 256>>>();
    rdeg_kernel<<<(NN + 255) / 256, 256>>>();

    // ---- layer 0 ----
    cudaMemsetAsync(aggp, 0, (size_t)NN * HID * sizeof(float));
    scatter_kernel<<<NE / 8, 256>>>(x);
    cudaMemsetAsync(bnp, 0, 2 * HID * sizeof(float));
    sage_gemm<128, 0><<<mgrid, 256>>>(x, ws0, wn0, b0, hA);
    bn_finalize_kernel<<<1, 128>>>(gamma0, beta0);
    bn_apply_kernel<<<agrid, 256>>>(hA, hB);

    // ---- layer 1 ----
    cudaMemsetAsync(aggp, 0, (size_t)NN * HID * sizeof(float));
    scatter_kernel<<<NE / 8, 256>>>(hB);
    cudaMemsetAsync(bnp, 0, 2 * HID * sizeof(float));
    sage_gemm<128, 0><<<mgrid, 256>>>(hB, ws1, wn1, b1, hA);
    bn_finalize_kernel<<<1, 128>>>(gamma1, beta1);
    bn_apply_kernel<<<agrid, 256>>>(hA, hB);

    // ---- layer 2 (+ fused log_softmax) ----
    cudaMemsetAsync(aggp, 0, (size_t)NN * HID * sizeof(float));
    scatter_kernel<<<NE / 8, 256>>>(hB);
    sage_gemm<64, 1><<<mgrid, 256>>>(hB, ws2, wn2, b2, out);
}

// round 3
// speedup vs baseline: 1.6642x; 1.6642x over previous
#include <cuda_runtime.h>
#include <math.h>
#include <stdint.h>

#define NN 100000
#define NE 1600000
#define HID 128
#define OUTF 64
#define NBLK ((NN + 255) / 256)   // 391 scan blocks

// ---------------- scratch (static device globals; no allocations) ----------
__device__ __align__(16) float g_rdeg[NN];
__device__ int   g_src[NE];
__device__ int   g_dst[NE];
__device__ int   g_cnt[NN];
__device__ int   g_off[NN];
__device__ int   g_cur[NN];
__device__ int   g_bsum[512];
__device__ int   g_csr[NE];
__device__ __align__(16) float g_agg[NN * HID];
__device__ __align__(16) float g_hA[NN * HID];
__device__ __align__(16) float g_hB[NN * HID];
__device__ __align__(16) float g_bn[4][HID];   // [0]=sum [1]=sumsq [2]=scale [3]=shift
__device__ int   g_idx64;

// ---------------- index width detection + conversion -----------------------
__global__ void detect_kernel(const unsigned int* p) {
    // If src is int64 (values < 2^31), every high 32-bit word is 0.
    int ok = 1;
    for (int i = 1; i < 128; i += 2)
        if (p[i] != 0u) ok = 0;
    g_idx64 = ok;
}

__global__ void convert_kernel(const void* srcv, const void* dstv) {
    int e = blockIdx.x * blockDim.x + threadIdx.x;
    if (e >= NE) return;
    int s, d;
    if (g_idx64) {
        s = (int)((const long long*)srcv)[e];
        d = (int)((const long long*)dstv)[e];
    } else {
        s = ((const int*)srcv)[e];
        d = ((const int*)dstv)[e];
    }
    g_src[e] = s;
    g_dst[e] = d;
    atomicAdd(&g_cnt[d], 1);
}

__global__ void rdeg_kernel() {
    int i = blockIdx.x * blockDim.x + threadIdx.x;
    if (i >= NN) return;
    g_rdeg[i] = 1.0f / (float)max(g_cnt[i], 1);
}

// ---------------- CSR build: 3-kernel exclusive scan + atomic fill ----------
__global__ void scan_local_kernel() {
    __shared__ int s[256];
    int i = blockIdx.x * 256 + threadIdx.x;
    int v = (i < NN) ? g_cnt[i] : 0;
    s[threadIdx.x] = v;
    __syncthreads();
#pragma unroll
    for (int off = 1; off < 256; off <<= 1) {
        int t = (threadIdx.x >= off) ? s[threadIdx.x - off] : 0;
        __syncthreads();
        s[threadIdx.x] += t;
        __syncthreads();
    }
    if (i < NN) g_off[i] = s[threadIdx.x] - v;      // exclusive within block
    if (threadIdx.x == 255) g_bsum[blockIdx.x] = s[255];
}

__global__ void scan_bsums_kernel() {
    __shared__ int s[512];
    int v = (threadIdx.x < NBLK) ? g_bsum[threadIdx.x] : 0;
    s[threadIdx.x] = v;
    __syncthreads();
#pragma unroll
    for (int off = 1; off < 512; off <<= 1) {
        int t = (threadIdx.x >= off) ? s[threadIdx.x - off] : 0;
        __syncthreads();
        s[threadIdx.x] += t;
        __syncthreads();
    }
    if (threadIdx.x < NBLK) g_bsum[threadIdx.x] = s[threadIdx.x] - v;  // exclusive
}

__global__ void scan_add_kernel() {
    int i = blockIdx.x * 256 + threadIdx.x;
    if (i >= NN) return;
    int o = g_off[i] + g_bsum[blockIdx.x];
    g_off[i] = o;
    g_cur[i] = o;
}

__global__ void csr_fill_kernel() {
    int e = blockIdx.x * blockDim.x + threadIdx.x;
    if (e >= NE) return;
    int pos = atomicAdd(&g_cur[g_dst[e]], 1);
    g_csr[pos] = g_src[e];
}

// ---------------- aggregation: warp-per-node CSR gather, rdeg folded in ----
__global__ __launch_bounds__(256) void aggregate_kernel(const float* __restrict__ h) {
    int node = (blockIdx.x * blockDim.x + threadIdx.x) >> 5;
    int lane = threadIdx.x & 31;
    if (node >= NN) return;
    int beg = g_off[node];
    int end = (node == NN - 1) ? NE : g_off[node + 1];
    float4 acc = make_float4(0.f, 0.f, 0.f, 0.f);
    int i = beg;
    // unroll-by-2 to expose MLP on the index + row loads
    for (; i + 2 <= end; i += 2) {
        int s0 = g_csr[i];
        int s1 = g_csr[i + 1];
        float4 v0 = ((const float4*)(h + (size_t)s0 * HID))[lane];
        float4 v1 = ((const float4*)(h + (size_t)s1 * HID))[lane];
        acc.x += v0.x + v1.x;
        acc.y += v0.y + v1.y;
        acc.z += v0.z + v1.z;
        acc.w += v0.w + v1.w;
    }
    for (; i < end; i++) {
        int s = g_csr[i];
        float4 v = ((const float4*)(h + (size_t)s * HID))[lane];
        acc.x += v.x; acc.y += v.y; acc.z += v.z; acc.w += v.w;
    }
    float r = g_rdeg[node];
    acc.x *= r; acc.y *= r; acc.z *= r; acc.w *= r;
    ((float4*)(g_agg + (size_t)node * HID))[lane] = acc;
}

// ---------------- fused GEMM: out = [h | agg] @ [Wself; Wneigh] + b --------
// Inner loop uses packed fma.rn.f32x2 (FFMA2): 2 MACs per fma-pipe issue.
// MODE 0: write raw linear out + accumulate BN sum/sumsq
// MODE 1: fused log_softmax over COLS(=64) columns
template<int COLS, int MODE>
__global__ __launch_bounds__(256, 2) void sage_gemm(
    const float* __restrict__ hin,
    const float* __restrict__ wself, const float* __restrict__ wneigh,
    const float* __restrict__ bias, float* __restrict__ outp)
{
    constexpr int TN = COLS / 16;
    constexpr int TN2 = TN / 2;
    __shared__ __align__(16) float As[16][132];
    __shared__ __align__(16) float Ws[16][COLS];
    __shared__ float sred[256];

    const int tid = threadIdx.x;
    const int tx = tid & 15;      // col group
    const int ty = tid >> 4;      // row group
    const int row0 = blockIdx.x * 128;

    unsigned long long acc2[8][TN2];
#pragma unroll
    for (int i = 0; i < 8; i++)
#pragma unroll
        for (int j = 0; j < TN2; j++) acc2[i][j] = 0ull;

    for (int kb = 0; kb < 256; kb += 16) {
        // --- load A tile: As[k][row], 128 rows x 16 k ---
#pragma unroll
        for (int it = 0; it < 2; it++) {
            int cidx = tid + it * 256;       // 0..511 float4 chunks
            int r  = cidx >> 2;              // 0..127
            int k4 = (cidx & 3) * 4;         // 0,4,8,12
            int row = row0 + r;
            int kk = kb + k4;
            float4 v = make_float4(0.f, 0.f, 0.f, 0.f);
            if (row < NN) {
                const float* base = (kk < 128)
                    ? (hin   + (size_t)row * HID + kk)
                    : (g_agg + (size_t)row * HID + (kk - 128));
                v = *(const float4*)base;
            }
            As[k4 + 0][r] = v.x;
            As[k4 + 1][r] = v.y;
            As[k4 + 2][r] = v.z;
            As[k4 + 3][r] = v.w;
        }
        // --- load W tile: Ws[k][c], 16 k x COLS ---
#pragma unroll
        for (int it = 0; it < (16 * COLS / 4) / 256; it++) {
            int cidx = tid + it * 256;
            int k  = cidx / (COLS / 4);
            int c4 = (cidx % (COLS / 4)) * 4;
            int kk = kb + k;
            const float* w = (kk < 128)
                ? (wself  + (size_t)kk * COLS + c4)
                : (wneigh + (size_t)(kk - 128) * COLS + c4);
            *(float4*)&Ws[k][c4] = *(const float4*)w;
        }
        __syncthreads();

#pragma unroll
        for (int k = 0; k < 16; k++) {
            float a[8];
            *(float4*)&a[0] = *(const float4*)&As[k][ty * 8];
            *(float4*)&a[4] = *(const float4*)&As[k][ty * 8 + 4];
            unsigned long long b2[TN2];
#pragma unroll
            for (int j = 0; j < TN2; j++)
                b2[j] = *(const unsigned long long*)&Ws[k][tx * TN + 2 * j];
#pragma unroll
            for (int i = 0; i < 8; i++) {
                unsigned long long a2;
                asm("mov.b64 %0, {%1, %1};" : "=l"(a2) : "f"(a[i]));
#pragma unroll
                for (int j = 0; j < TN2; j++)
                    asm("fma.rn.f32x2 %0, %1, %2, %0;"
                        : "+l"(acc2[i][j]) : "l"(a2), "l"(b2[j]));
            }
        }
        __syncthreads();
    }

    // unpack accumulators
    float acc[8][TN];
#pragma unroll
    for (int i = 0; i < 8; i++)
#pragma unroll
        for (int j = 0; j < TN2; j++)
            asm("mov.b64 {%0, %1}, %2;"
                : "=f"(acc[i][2 * j]), "=f"(acc[i][2 * j + 1]) : "l"(acc2[i][j]));

    float bfr[TN];
#pragma unroll
    for (int j = 0; j < TN; j++) bfr[j] = bias[tx * TN + j];

    if (MODE == 0) {
        float vsum[TN], vsq[TN];
#pragma unroll
        for (int j = 0; j < TN; j++) { vsum[j] = 0.f; vsq[j] = 0.f; }
#pragma unroll
        for (int i = 0; i < 8; i++) {
            int row = row0 + ty * 8 + i;
            if (row < NN) {
                float o[TN];
#pragma unroll
                for (int j = 0; j < TN; j++) {
                    float v = acc[i][j] + bfr[j];
                    o[j] = v;
                    vsum[j] += v;
                    vsq[j]  += v * v;
                }
#pragma unroll
                for (int j = 0; j < TN; j += 4)
                    *(float4*)(outp + (size_t)row * COLS + tx * TN + j) = *(float4*)&o[j];
            }
        }
        // block-level BN partial reduce, then one global atomic per column
        sred[tid] = 0.0f;
        __syncthreads();
#pragma unroll
        for (int j = 0; j < TN; j++) {
            atomicAdd(&sred[tx * TN + j], vsum[j]);
            atomicAdd(&sred[128 + tx * TN + j], vsq[j]);
        }
        __syncthreads();
        if (tid < 128) {
            atomicAdd(&g_bn[0][tid], sred[tid]);
            atomicAdd(&g_bn[1][tid], sred[128 + tid]);
        }
    } else {
        // fused log_softmax across COLS=64: 16 threads (tx) own 4 cols each;
        // butterfly over low 4 lane bits reduces across tx within the warp.
#pragma unroll
        for (int i = 0; i < 8; i++) {
            int row = row0 + ty * 8 + i;
            float v[TN];
            float m = -INFINITY;
#pragma unroll
            for (int j = 0; j < TN; j++) {
                v[j] = acc[i][j] + bfr[j];
                m = fmaxf(m, v[j]);
            }
#pragma unroll
            for (int off = 8; off > 0; off >>= 1)
                m = fmaxf(m, __shfl_xor_sync(0xffffffffu, m, off));
            float s = 0.0f;
#pragma unroll
            for (int j = 0; j < TN; j++) s += expf(v[j] - m);
#pragma unroll
            for (int off = 8; off > 0; off >>= 1)
                s += __shfl_xor_sync(0xffffffffu, s, off);
            float lse = m + logf(s);
            if (row < NN) {
                float o[TN];
#pragma unroll
                for (int j = 0; j < TN; j++) o[j] = v[j] - lse;
                *(float4*)(outp + (size_t)row * COLS + tx * TN) = *(float4*)&o[0];
            }
        }
    }
}

// ---------------- BN finalize + apply --------------------------------------
__global__ void bn_finalize_kernel(const float* __restrict__ gamma,
                                   const float* __restrict__ beta) {
    int c = threadIdx.x;
    if (c >= HID) return;
    float s  = g_bn[0][c];
    float sq = g_bn[1][c];
    float mu  = s / (float)NN;
    float var = sq / (float)NN - mu * mu;
    float sc = gamma[c] * rsqrtf(var + 1e-5f);
    g_bn[2][c] = sc;
    g_bn[3][c] = beta[c] - mu * sc;
}

__global__ __launch_bounds__(256) void bn_apply_kernel(const float* __restrict__ in,
                                                       float* __restrict__ outp) {
    int idx = blockIdx.x * blockDim.x + threadIdx.x;   // float4 index
    if (idx >= NN * (HID / 4)) return;
    float4 v = ((const float4*)in)[idx];
    int c = (idx & (HID / 4 - 1)) * 4;
    float4 o;
    o.x = fmaxf(fmaf(v.x, g_bn[2][c + 0], g_bn[3][c + 0]), 0.0f);
    o.y = fmaxf(fmaf(v.y, g_bn[2][c + 1], g_bn[3][c + 1]), 0.0f);
    o.z = fmaxf(fmaf(v.z, g_bn[2][c + 2], g_bn[3][c + 2]), 0.0f);
    o.w = fmaxf(fmaf(v.w, g_bn[2][c + 3], g_bn[3][c + 3]), 0.0f);
    ((float4*)outp)[idx] = o;
}

// ---------------- launch ----------------------------------------------------
extern "C" void kernel_launch(void* const* d_in, const int* in_sizes, int n_in,
                              void* d_out, int out_size) {
    const float* x   = (const float*)d_in[0];
    const void*  src = d_in[1];
    const void*  dst = d_in[2];
    const float* ws0 = (const float*)d_in[3];
    const float* wn0 = (const float*)d_in[4];
    const float* b0  = (const float*)d_in[5];
    const float* ws1 = (const float*)d_in[6];
    const float* wn1 = (const float*)d_in[7];
    const float* b1  = (const float*)d_in[8];
    const float* ws2 = (const float*)d_in[9];
    const float* wn2 = (const float*)d_in[10];
    const float* b2  = (const float*)d_in[11];
    const float* gamma0 = (const float*)d_in[12];
    const float* beta0  = (const float*)d_in[13];
    const float* gamma1 = (const float*)d_in[14];
    const float* beta1  = (const float*)d_in[15];
    float* out = (float*)d_out;

    void *cntp, *bnp, *hAp, *hBp;
    cudaGetSymbolAddress(&cntp, g_cnt);
    cudaGetSymbolAddress(&bnp,  g_bn);
    cudaGetSymbolAddress(&hAp,  g_hA);
    cudaGetSymbolAddress(&hBp,  g_hB);
    float* hA = (float*)hAp;
    float* hB = (float*)hBp;

    const int egrid = (NE + 255) / 256;
    const int mgrid = (NN + 127) / 128;                  // 782
    const int agrid = (NN * (HID / 4) + 255) / 256;
    const int ngrid = (NN * 32 + 255) / 256;             // warp-per-node

    // ---- index convert + CSR build (once per launch) ----
    detect_kernel<<<1, 1>>>((const unsigned int*)src);
    cudaMemsetAsync(cntp, 0, NN * sizeof(int));
    convert_kernel<<<egrid, 256>>>(src, dst);
    rdeg_kernel<<<NBLK, 256>>>();
    scan_local_kernel<<<NBLK, 256>>>();
    scan_bsums_kernel<<<1, 512>>>();
    scan_add_kernel<<<NBLK, 256>>>();
    csr_fill_kernel<<<egrid, 256>>>();

    // ---- layer 0 ----
    aggregate_kernel<<<ngrid, 256>>>(x);
    cudaMemsetAsync(bnp, 0, 2 * HID * sizeof(float));
    sage_gemm<128, 0><<<mgrid, 256>>>(x, ws0, wn0, b0, hA);
    bn_finalize_kernel<<<1, 128>>>(gamma0, beta0);
    bn_apply_kernel<<<agrid, 256>>>(hA, hB);

    // ---- layer 1 ----
    aggregate_kernel<<<ngrid, 256>>>(hB);
    cudaMemsetAsync(bnp, 0, 2 * HID * sizeof(float));
    sage_gemm<128, 0><<<mgrid, 256>>>(hB, ws1, wn1, b1, hA);
    bn_finalize_kernel<<<1, 128>>>(gamma1, beta1);
    bn_apply_kernel<<<agrid, 256>>>(hA, hB);

    // ---- layer 2 (+ fused log_softmax) ----
    aggregate_kernel<<<ngrid, 256>>>(hB);
    sage_gemm<64, 1><<<mgrid, 256>>>(hB, ws2, wn2, b2, out);
}

// round 8
// speedup vs baseline: 1.6654x; 1.0007x over previous
#include <cuda_runtime.h>
#include <cuda_bf16.h>
#include <math.h>
#include <stdint.h>

#define NN 100000
#define NE 1600000
#define HID 128
#define OUTF 64
#define NBLK ((NN + 255) / 256)   // 391 scan blocks

// ---------------- scratch (static device globals; no allocations) ----------
__device__ __align__(16) float g_rdeg[NN];
__device__ int   g_src[NE];
__device__ int   g_dst[NE];
__device__ int   g_cnt[NN];
__device__ int   g_off[NN];
__device__ int   g_cur[NN];
__device__ int   g_bsum[512];
__device__ int   g_csr[NE];
__device__ __align__(16) float g_hA[NN * HID];            // GEMM linear out
__device__ __align__(16) float g_hB[NN * HID];            // post BN+ReLU (fp32, gather src)
__device__ __align__(16) __nv_bfloat16 g_Ahi[NN * 256];   // A = [h | agg] hi split
__device__ __align__(16) __nv_bfloat16 g_Alo[NN * 256];   // A lo split
__device__ __align__(16) __nv_bfloat16 g_Whi[HID * 256];  // W^T = [N][K=256] hi
__device__ __align__(16) __nv_bfloat16 g_Wlo[HID * 256];  // W^T lo
__device__ __align__(16) float g_bn[4][HID];   // [0]=sum [1]=sumsq [2]=scale [3]=shift
__device__ int   g_idx64;

// ---------------- ptx helpers (all sm_80-era, no arch-'a' features) --------
__device__ __forceinline__ uint32_t smem_u32(const void* p) {
    uint32_t a;
    asm("{ .reg .u64 t; cvta.to.shared.u64 t, %1; cvt.u32.u64 %0, t; }"
        : "=r"(a) : "l"(p));
    return a;
}
__device__ __forceinline__ uint32_t sw128(uint32_t b) { return b ^ ((b >> 3) & 0x70); }

__device__ __forceinline__ void cp16(uint32_t sdst, const void* gsrc) {
    asm volatile("cp.async.cg.shared.global [%0], [%1], 16;"
                 :: "r"(sdst), "l"(gsrc) : "memory");
}
__device__ __forceinline__ void cp_commit() {
    asm volatile("cp.async.commit_group;" ::: "memory");
}
template<int W> __device__ __forceinline__ void cp_wait() {
    asm volatile("cp.async.wait_group %0;" :: "n"(W) : "memory");
}
__device__ __forceinline__ void ldm_x4(uint32_t* r, uint32_t a) {
    asm volatile("ldmatrix.sync.aligned.m8n8.x4.shared.b16 {%0,%1,%2,%3}, [%4];"
                 : "=r"(r[0]), "=r"(r[1]), "=r"(r[2]), "=r"(r[3]) : "r"(a));
}
__device__ __forceinline__ void ldm_x2(uint32_t* r, uint32_t a) {
    asm volatile("ldmatrix.sync.aligned.m8n8.x2.shared.b16 {%0,%1}, [%2];"
                 : "=r"(r[0]), "=r"(r[1]) : "r"(a));
}
__device__ __forceinline__ void mma_bf16(float* d, const uint32_t* a, const uint32_t* b) {
    asm volatile("mma.sync.aligned.m16n8k16.row.col.f32.bf16.bf16.f32 "
                 "{%0,%1,%2,%3}, {%4,%5,%6,%7}, {%8,%9}, {%0,%1,%2,%3};"
                 : "+f"(d[0]), "+f"(d[1]), "+f"(d[2]), "+f"(d[3])
                 : "r"(a[0]), "r"(a[1]), "r"(a[2]), "r"(a[3]),
                   "r"(b[0]), "r"(b[1]));
}
__device__ __forceinline__ uint32_t pack2(float a, float b) {
    __nv_bfloat162 t = __floats2bfloat162_rn(a, b);
    return *(uint32_t*)&t;
}
__device__ __forceinline__ void split_store(__nv_bfloat16* hi, __nv_bfloat16* lo,
                                            size_t off, float4 v) {
    float hx = __bfloat162float(__float2bfloat16_rn(v.x));
    float hy = __bfloat162float(__float2bfloat16_rn(v.y));
    float hz = __bfloat162float(__float2bfloat16_rn(v.z));
    float hw = __bfloat162float(__float2bfloat16_rn(v.w));
    uint2 H = make_uint2(pack2(v.x, v.y), pack2(v.z, v.w));
    uint2 L = make_uint2(pack2(v.x - hx, v.y - hy), pack2(v.z - hz, v.w - hw));
    *(uint2*)(hi + off) = H;
    *(uint2*)(lo + off) = L;
}

// ---------------- index width detection + conversion -----------------------
__global__ void detect_kernel(const unsigned int* p) {
    int ok = 1;
    for (int i = 1; i < 128; i += 2)
        if (p[i] != 0u) ok = 0;
    g_idx64 = ok;
}

__global__ void convert_kernel(const void* srcv, const void* dstv) {
    int e = blockIdx.x * blockDim.x + threadIdx.x;
    if (e >= NE) return;
    int s, d;
    if (g_idx64) {
        s = (int)((const long long*)srcv)[e];
        d = (int)((const long long*)dstv)[e];
    } else {
        s = ((const int*)srcv)[e];
        d = ((const int*)dstv)[e];
    }
    g_src[e] = s;
    g_dst[e] = d;
    atomicAdd(&g_cnt[d], 1);
}

__global__ void rdeg_kernel() {
    int i = blockIdx.x * blockDim.x + threadIdx.x;
    if (i >= NN) return;
    g_rdeg[i] = 1.0f / (float)max(g_cnt[i], 1);
}

// ---------------- CSR build: 3-kernel exclusive scan + atomic fill ----------
__global__ void scan_local_kernel() {
    __shared__ int s[256];
    int i = blockIdx.x * 256 + threadIdx.x;
    int v = (i < NN) ? g_cnt[i] : 0;
    s[threadIdx.x] = v;
    __syncthreads();
#pragma unroll
    for (int off = 1; off < 256; off <<= 1) {
        int t = (threadIdx.x >= off) ? s[threadIdx.x - off] : 0;
        __syncthreads();
        s[threadIdx.x] += t;
        __syncthreads();
    }
    if (i < NN) g_off[i] = s[threadIdx.x] - v;
    if (threadIdx.x == 255) g_bsum[blockIdx.x] = s[255];
}

__global__ void scan_bsums_kernel() {
    __shared__ int s[512];
    int v = (threadIdx.x < NBLK) ? g_bsum[threadIdx.x] : 0;
    s[threadIdx.x] = v;
    __syncthreads();
#pragma unroll
    for (int off = 1; off < 512; off <<= 1) {
        int t = (threadIdx.x >= off) ? s[threadIdx.x - off] : 0;
        __syncthreads();
        s[threadIdx.x] += t;
        __syncthreads();
    }
    if (threadIdx.x < NBLK) g_bsum[threadIdx.x] = s[threadIdx.x] - v;
}

__global__ void scan_add_kernel() {
    int i = blockIdx.x * 256 + threadIdx.x;
    if (i >= NN) return;
    int o = g_off[i] + g_bsum[blockIdx.x];
    g_off[i] = o;
    g_cur[i] = o;
}

__global__ void csr_fill_kernel() {
    int e = blockIdx.x * blockDim.x + threadIdx.x;
    if (e >= NE) return;
    int pos = atomicAdd(&g_cur[g_dst[e]], 1);
    g_csr[pos] = g_src[e];
}

// ---------------- aggregation: CSR gather -> bf16 hi/lo split (A cols 128+) -
__global__ __launch_bounds__(256) void aggregate_kernel(const float* __restrict__ h) {
    int node = (blockIdx.x * blockDim.x + threadIdx.x) >> 5;
    int lane = threadIdx.x & 31;
    if (node >= NN) return;
    int beg = g_off[node];
    int end = (node == NN - 1) ? NE : g_off[node + 1];
    float4 acc = make_float4(0.f, 0.f, 0.f, 0.f);
    int i = beg;
    for (; i + 2 <= end; i += 2) {
        int s0 = g_csr[i];
        int s1 = g_csr[i + 1];
        float4 v0 = ((const float4*)(h + (size_t)s0 * HID))[lane];
        float4 v1 = ((const float4*)(h + (size_t)s1 * HID))[lane];
        acc.x += v0.x + v1.x;
        acc.y += v0.y + v1.y;
        acc.z += v0.z + v1.z;
        acc.w += v0.w + v1.w;
    }
    for (; i < end; i++) {
        int s = g_csr[i];
        float4 v = ((const float4*)(h + (size_t)s * HID))[lane];
        acc.x += v.x; acc.y += v.y; acc.z += v.z; acc.w += v.w;
    }
    float r = g_rdeg[node];
    acc.x *= r; acc.y *= r; acc.z *= r; acc.w *= r;
    split_store(g_Ahi, g_Alo, (size_t)node * 256 + 128 + lane * 4, acc);
}

// ---------------- x split (layer-0 self cols 0..127) -----------------------
__global__ __launch_bounds__(256) void xsplit_kernel(const float* __restrict__ x) {
    int idx = blockIdx.x * blockDim.x + threadIdx.x;   // float4 units
    if (idx >= NN * 32) return;
    float4 v = ((const float4*)x)[idx];
    int row = idx >> 5;
    int c = (idx & 31) * 4;
    split_store(g_Ahi, g_Alo, (size_t)row * 256 + c, v);
}

// ---------------- weight prep: transpose + split ---------------------------
__global__ void wprep_kernel(const float* __restrict__ ws,
                             const float* __restrict__ wn, int cols) {
    int i = blockIdx.x * blockDim.x + threadIdx.x;     // over cols*256
    if (i >= cols * 256) return;
    int n = i >> 8;
    int k = i & 255;
    float v = (k < 128) ? ws[k * cols + n] : wn[(k - 128) * cols + n];
    __nv_bfloat16 h = __float2bfloat16_rn(v);
    g_Whi[n * 256 + k] = h;
    g_Wlo[n * 256 + k] = __float2bfloat16_rn(v - __bfloat162float(h));
}

// ---------------- mma.sync GEMM: D = A(128x256) @ W^T, bf16x2 split ---------
// Block 256 thr (8 warps), tile 128xCOLS, KC=32 double-buffered cp.async.
// Warp grid: COLS=128 -> 4Mx2N (warp 32x64); COLS=64 -> 8Mx1N (warp 16x64)
// so one warp owns ALL columns of its rows (log_softmax fully intra-warp).
// smem stage row = 128B: [32 bf16 hi | 32 bf16 lo], SW128-swizzled.
// MODE 0: out = D + bias (fp32). MODE 1: out = log_softmax(D + bias) rowwise.
template<int COLS, int MODE>
__global__ __launch_bounds__(256) void sage_mma(
    const float* __restrict__ bias, float* __restrict__ outp)
{
    extern __shared__ __align__(1024) char smem[];
    constexpr int BB  = COLS * 128;          // B stage bytes
    constexpr int A1o = 16384;
    constexpr int B0o = 32768;
    constexpr int B1o = 32768 + BB;
    constexpr int NWN = (COLS == 128) ? 2 : 1;   // warps along N
    constexpr int NWM = 8 / NWN;                 // warps along M
    constexpr int MI  = 128 / (NWM * 16);        // m16 steps per warp (2 or 1)
    constexpr int WARP_N = COLS / NWN;           // 64
    constexpr int NI  = WARP_N / 8;              // 8

    const int tid  = threadIdx.x;
    const int wid  = tid >> 5;
    const int lane = tid & 31;
    const int wm   = wid / NWN;
    const int wn   = wid % NWN;
    const int row0 = blockIdx.x * 128;
    const uint32_t sb = smem_u32(smem);

    // ldmatrix per-lane base indices
    const int arow = wm * (MI * 16) + (lane & 15);   // + mi*16
    const int acb  = (lane >> 4) * 16;               // 16B chunk within k16
    const int brow = wn * WARP_N + (lane & 7);       // + ni*8
    const int bcb  = ((lane >> 3) & 1) * 16;

    float acc[MI][NI][4];
#pragma unroll
    for (int mi = 0; mi < MI; mi++)
#pragma unroll
        for (int ni = 0; ni < NI; ni++)
#pragma unroll
            for (int q = 0; q < 4; q++) acc[mi][ni][q] = 0.0f;

    auto load_stage = [&](int ks, int buf) {
        uint32_t Ab = sb + (buf ? A1o : 0);
        uint32_t Bb = sb + (buf ? B1o : B0o);
#pragma unroll
        for (int i = 0; i < 4; i++) {                // A: 1024 16B chunks
            int u = tid + i * 256;
            int r = u >> 3, c = u & 7;
            int rowg = min(row0 + r, NN - 1);
            const __nv_bfloat16* g = (c < 4 ? g_Ahi : g_Alo)
                                   + (size_t)rowg * 256 + ks * 32 + (c & 3) * 8;
            cp16(Ab + sw128(r * 128 + c * 16), g);
        }
#pragma unroll
        for (int i = 0; i < COLS / 32; i++) {        // B: COLS*8 chunks
            int u = tid + i * 256;
            int n = u >> 3, c = u & 7;
            const __nv_bfloat16* g = (c < 4 ? g_Whi : g_Wlo)
                                   + (size_t)n * 256 + ks * 32 + (c & 3) * 8;
            cp16(Bb + sw128(n * 128 + c * 16), g);
        }
    };

    auto compute_stage = [&](int buf) {
        uint32_t Ab = sb + (buf ? A1o : 0);
        uint32_t Bb = sb + (buf ? B1o : B0o);
#pragma unroll
        for (int kk = 0; kk < 2; kk++) {             // two k16 steps per stage
            uint32_t bh[NI][2], bl[NI][2];
#pragma unroll
            for (int ni = 0; ni < NI; ni++) {
                uint32_t off = (uint32_t)(brow + ni * 8) * 128 + kk * 32 + bcb;
                ldm_x2(bh[ni], Bb + sw128(off));
                ldm_x2(bl[ni], Bb + sw128(off + 64));
            }
#pragma unroll
            for (int mi = 0; mi < MI; mi++) {
                uint32_t ah[4], al[4];
                uint32_t off = (uint32_t)(arow + mi * 16) * 128 + kk * 32 + acb;
                ldm_x4(ah, Ab + sw128(off));
                ldm_x4(al, Ab + sw128(off + 64));
#pragma unroll
                for (int ni = 0; ni < NI; ni++) {
                    mma_bf16(acc[mi][ni], ah, bh[ni]);   // hi*hi
                    mma_bf16(acc[mi][ni], ah, bl[ni]);   // hi*lo
                    mma_bf16(acc[mi][ni], al, bh[ni]);   // lo*hi
                }
            }
        }
    };

    load_stage(0, 0);
    cp_commit();
    for (int ks = 0; ks < 8; ks++) {
        if (ks < 7) {
            load_stage(ks + 1, (ks + 1) & 1);
            cp_commit();
            cp_wait<1>();
        } else {
            cp_wait<0>();
        }
        __syncthreads();
        compute_stage(ks & 1);
        __syncthreads();
    }

    // ---- epilogue: add bias into acc first ----
#pragma unroll
    for (int mi = 0; mi < MI; mi++)
#pragma unroll
        for (int ni = 0; ni < NI; ni++) {
            int c = wn * WARP_N + ni * 8 + (lane & 3) * 2;
            float b0 = __ldg(bias + c), b1 = __ldg(bias + c + 1);
            acc[mi][ni][0] += b0; acc[mi][ni][1] += b1;
            acc[mi][ni][2] += b0; acc[mi][ni][3] += b1;
        }

    const int r_base = row0 + wm * (MI * 16) + (lane >> 2);

    if (MODE == 0) {
#pragma unroll
        for (int mi = 0; mi < MI; mi++) {
            int rA = r_base + mi * 16;
            int rB = rA + 8;
#pragma unroll
            for (int ni = 0; ni < NI; ni++) {
                int c = wn * WARP_N + ni * 8 + (lane & 3) * 2;
                if (rA < NN) {
                    float2 o = make_float2(acc[mi][ni][0], acc[mi][ni][1]);
                    *(float2*)(outp + (size_t)rA * COLS + c) = o;
                }
                if (rB < NN) {
                    float2 o = make_float2(acc[mi][ni][2], acc[mi][ni][3]);
                    *(float2*)(outp + (size_t)rB * COLS + c) = o;
                }
            }
        }
    } else {
        // log_softmax over COLS=64: warp owns all 64 cols of each row
        // (NWN==1). Cols of one row live in lanes sharing lane>>2, spread
        // over lane&3 and ni -> xor-shuffles 1,2 complete the reduction.
#pragma unroll
        for (int mi = 0; mi < MI; mi++) {
            float mA = -INFINITY, mB = -INFINITY;
#pragma unroll
            for (int ni = 0; ni < NI; ni++) {
                mA = fmaxf(mA, fmaxf(acc[mi][ni][0], acc[mi][ni][1]));
                mB = fmaxf(mB, fmaxf(acc[mi][ni][2], acc[mi][ni][3]));
            }
#pragma unroll
            for (int off = 1; off <= 2; off <<= 1) {
                mA = fmaxf(mA, __shfl_xor_sync(0xffffffffu, mA, off));
                mB = fmaxf(mB, __shfl_xor_sync(0xffffffffu, mB, off));
            }
            float sA = 0.f, sB = 0.f;
#pragma unroll
            for (int ni = 0; ni < NI; ni++) {
                sA += expf(acc[mi][ni][0] - mA) + expf(acc[mi][ni][1] - mA);
                sB += expf(acc[mi][ni][2] - mB) + expf(acc[mi][ni][3] - mB);
            }
#pragma unroll
            for (int off = 1; off <= 2; off <<= 1) {
                sA += __shfl_xor_sync(0xffffffffu, sA, off);
                sB += __shfl_xor_sync(0xffffffffu, sB, off);
            }
            float lseA = mA + logf(sA);
            float lseB = mB + logf(sB);
            int rA = r_base + mi * 16;
            int rB = rA + 8;
#pragma unroll
            for (int ni = 0; ni < NI; ni++) {
                int c = wn * WARP_N + ni * 8 + (lane & 3) * 2;
                if (rA < NN) {
                    float2 o = make_float2(acc[mi][ni][0] - lseA, acc[mi][ni][1] - lseA);
                    *(float2*)(outp + (size_t)rA * COLS + c) = o;
                }
                if (rB < NN) {
                    float2 o = make_float2(acc[mi][ni][2] - lseB, acc[mi][ni][3] - lseB);
                    *(float2*)(outp + (size_t)rB * COLS + c) = o;
                }
            }
        }
    }
}

// ---------------- BN stats / finalize / apply -------------------------------
__global__ __launch_bounds__(256) void bn_stats_kernel(const float* __restrict__ h) {
    __shared__ float ss[256], qq[256];
    int col = threadIdx.x & 127;
    int half = threadIdx.x >> 7;
    int r0 = blockIdx.x * 256 + half * 128;
    float s = 0.f, q = 0.f;
    for (int i = 0; i < 128; i++) {
        int r = r0 + i;
        if (r < NN) {
            float v = h[(size_t)r * HID + col];
            s += v;
            q += v * v;
        }
    }
    ss[threadIdx.x] = s;
    qq[threadIdx.x] = q;
    __syncthreads();
    if (half == 0) {
        atomicAdd(&g_bn[0][col], s + ss[threadIdx.x + 128]);
        atomicAdd(&g_bn[1][col], q + qq[threadIdx.x + 128]);
    }
}

__global__ void bn_finalize_kernel(const float* __restrict__ gamma,
                                   const float* __restrict__ beta) {
    int c = threadIdx.x;
    if (c >= HID) return;
    float s  = g_bn[0][c];
    float sq = g_bn[1][c];
    float mu  = s / (float)NN;
    float var = sq / (float)NN - mu * mu;
    float sc = gamma[c] * rsqrtf(var + 1e-5f);
    g_bn[2][c] = sc;
    g_bn[3][c] = beta[c] - mu * sc;
}

// BN + ReLU -> fp32 (next gather source) + bf16 hi/lo split (A cols 0..127)
__global__ __launch_bounds__(256) void bn_apply_kernel(const float* __restrict__ in,
                                                       float* __restrict__ outp) {
    int idx = blockIdx.x * blockDim.x + threadIdx.x;   // float4 units
    if (idx >= NN * 32) return;
    float4 v = ((const float4*)in)[idx];
    int row = idx >> 5;
    int c = (idx & 31) * 4;
    float4 o;
    o.x = fmaxf(fmaf(v.x, g_bn[2][c + 0], g_bn[3][c + 0]), 0.0f);
    o.y = fmaxf(fmaf(v.y, g_bn[2][c + 1], g_bn[3][c + 1]), 0.0f);
    o.z = fmaxf(fmaf(v.z, g_bn[2][c + 2], g_bn[3][c + 2]), 0.0f);
    o.w = fmaxf(fmaf(v.w, g_bn[2][c + 3], g_bn[3][c + 3]), 0.0f);
    ((float4*)outp)[idx] = o;
    split_store(g_Ahi, g_Alo, (size_t)row * 256 + c, o);
}

// ---------------- launch ----------------------------------------------------
extern "C" void kernel_launch(void* const* d_in, const int* in_sizes, int n_in,
                              void* d_out, int out_size) {
    const float* x   = (const float*)d_in[0];
    const void*  src = d_in[1];
    const void*  dst = d_in[2];
    const float* ws0 = (const float*)d_in[3];
    const float* wn0 = (const float*)d_in[4];
    const float* b0  = (const float*)d_in[5];
    const float* ws1 = (const float*)d_in[6];
    const float* wn1 = (const float*)d_in[7];
    const float* b1  = (const float*)d_in[8];
    const float* ws2 = (const float*)d_in[9];
    const float* wn2 = (const float*)d_in[10];
    const float* b2  = (const float*)d_in[11];
    const float* gamma0 = (const float*)d_in[12];
    const float* beta0  = (const float*)d_in[13];
    const float* gamma1 = (const float*)d_in[14];
    const float* beta1  = (const float*)d_in[15];
    float* out = (float*)d_out;

    void *cntp, *bnp, *hAp, *hBp;
    cudaGetSymbolAddress(&cntp, g_cnt);
    cudaGetSymbolAddress(&bnp,  g_bn);
    cudaGetSymbolAddress(&hAp,  g_hA);
    cudaGetSymbolAddress(&hBp,  g_hB);
    float* hA = (float*)hAp;
    float* hB = (float*)hBp;

    const int SMEM128 = 2 * 16384 + 2 * 128 * 128;   // 65536
    const int SMEM64  = 2 * 16384 + 2 * 64 * 128;    // 49152
    cudaFuncSetAttribute(sage_mma<128, 0>, cudaFuncAttributeMaxDynamicSharedMemorySize, SMEM128);
    cudaFuncSetAttribute(sage_mma<64, 1>,  cudaFuncAttributeMaxDynamicSharedMemorySize, SMEM64);

    const int egrid = (NE + 255) / 256;
    const int mgrid = (NN + 127) / 128;                  // 782
    const int agrid = (NN * 32 + 255) / 256;             // float4 grid over NN*128
    const int ngrid = (NN * 32 + 255) / 256;             // warp-per-node

    // ---- index convert + CSR build (once per launch) ----
    detect_kernel<<<1, 1>>>((const unsigned int*)src);
    cudaMemsetAsync(cntp, 0, NN * sizeof(int));
    convert_kernel<<<egrid, 256>>>(src, dst);
    rdeg_kernel<<<NBLK, 256>>>();
    scan_local_kernel<<<NBLK, 256>>>();
    scan_bsums_kernel<<<1, 512>>>();
    scan_add_kernel<<<NBLK, 256>>>();
    csr_fill_kernel<<<egrid, 256>>>();

    // ---- layer 0 ----
    xsplit_kernel<<<agrid, 256>>>(x);
    aggregate_kernel<<<ngrid, 256>>>(x);
    wprep_kernel<<<HID, 256>>>(ws0, wn0, HID);
    sage_mma<128, 0><<<mgrid, 256, SMEM128>>>(b0, hA);
    cudaMemsetAsync(bnp, 0, 2 * HID * sizeof(float));
    bn_stats_kernel<<<NBLK, 256>>>(hA);
    bn_finalize_kernel<<<1, 128>>>(gamma0, beta0);
    bn_apply_kernel<<<agrid, 256>>>(hA, hB);

    // ---- layer 1 ----
    aggregate_kernel<<<ngrid, 256>>>(hB);
    wprep_kernel<<<HID, 256>>>(ws1, wn1, HID);
    sage_mma<128, 0><<<mgrid, 256, SMEM128>>>(b1, hA);
    cudaMemsetAsync(bnp, 0, 2 * HID * sizeof(float));
    bn_stats_kernel<<<NBLK, 256>>>(hA);
    bn_finalize_kernel<<<1, 128>>>(gamma1, beta1);
    bn_apply_kernel<<<agrid, 256>>>(hA, hB);

    // ---- layer 2 (+ fused log_softmax) ----
    aggregate_kernel<<<ngrid, 256>>>(hB);
    wprep_kernel<<<OUTF, 256>>>(ws2, wn2, OUTF);
    sage_mma<64, 1><<<mgrid, 256, SMEM64>>>(b2, out);
}

// round 9
// speedup vs baseline: 1.6996x; 1.0205x over previous
#include <cuda_runtime.h>
#include <cuda_bf16.h>
#include <math.h>
#include <stdint.h>

#define NN 100000
#define NE 1600000
#define HID 128
#define OUTF 64
#define NBLK ((NN + 255) / 256)   // 391 scan_local blocks

// ---------------- scratch (static device globals; no allocations) ----------
__device__ int   g_src[NE];
__device__ int   g_dst[NE];
__device__ int   g_cnt[NN];
__device__ int   g_off[NN];
__device__ int   g_cur[NN];
__device__ int   g_bsum[512];
__device__ int   g_csr[NE];
__device__ __align__(16) float g_hA[NN * HID];            // GEMM linear out
__device__ __align__(16) float g_hB[NN * HID];            // post BN+ReLU (fp32, gather src)
__device__ __align__(16) __nv_bfloat16 g_Ahi[NN * 256];   // A = [h | agg] hi split
__device__ __align__(16) __nv_bfloat16 g_Alo[NN * 256];   // A lo split
__device__ __align__(16) __nv_bfloat16 g_Whi[320 * 256];  // W^T hi, layers at 0/32768/65536
__device__ __align__(16) __nv_bfloat16 g_Wlo[320 * 256];  // W^T lo
__device__ __align__(16) float g_bn[2][HID];              // [0]=sum [1]=sumsq

// ---------------- ptx helpers (all sm_80-era, no arch-'a' features) --------
__device__ __forceinline__ uint32_t smem_u32(const void* p) {
    uint32_t a;
    asm("{ .reg .u64 t; cvta.to.shared.u64 t, %1; cvt.u32.u64 %0, t; }"
        : "=r"(a) : "l"(p));
    return a;
}
__device__ __forceinline__ uint32_t sw128(uint32_t b) { return b ^ ((b >> 3) & 0x70); }

__device__ __forceinline__ void cp16(uint32_t sdst, const void* gsrc) {
    asm volatile("cp.async.cg.shared.global [%0], [%1], 16;"
                 :: "r"(sdst), "l"(gsrc) : "memory");
}
__device__ __forceinline__ void cp_commit() {
    asm volatile("cp.async.commit_group;" ::: "memory");
}
template<int W> __device__ __forceinline__ void cp_wait() {
    asm volatile("cp.async.wait_group %0;" :: "n"(W) : "memory");
}
__device__ __forceinline__ void ldm_x4(uint32_t* r, uint32_t a) {
    asm volatile("ldmatrix.sync.aligned.m8n8.x4.shared.b16 {%0,%1,%2,%3}, [%4];"
                 : "=r"(r[0]), "=r"(r[1]), "=r"(r[2]), "=r"(r[3]) : "r"(a));
}
__device__ __forceinline__ void ldm_x2(uint32_t* r, uint32_t a) {
    asm volatile("ldmatrix.sync.aligned.m8n8.x2.shared.b16 {%0,%1}, [%2];"
                 : "=r"(r[0]), "=r"(r[1]) : "r"(a));
}
__device__ __forceinline__ void mma_bf16(float* d, const uint32_t* a, const uint32_t* b) {
    asm volatile("mma.sync.aligned.m16n8k16.row.col.f32.bf16.bf16.f32 "
                 "{%0,%1,%2,%3}, {%4,%5,%6,%7}, {%8,%9}, {%0,%1,%2,%3};"
                 : "+f"(d[0]), "+f"(d[1]), "+f"(d[2]), "+f"(d[3])
                 : "r"(a[0]), "r"(a[1]), "r"(a[2]), "r"(a[3]),
                   "r"(b[0]), "r"(b[1]));
}
__device__ __forceinline__ uint32_t pack2(float a, float b) {
    __nv_bfloat162 t = __floats2bfloat162_rn(a, b);
    return *(uint32_t*)&t;
}
__device__ __forceinline__ void split_store(__nv_bfloat16* hi, __nv_bfloat16* lo,
                                            size_t off, float4 v) {
    float hx = __bfloat162float(__float2bfloat16_rn(v.x));
    float hy = __bfloat162float(__float2bfloat16_rn(v.y));
    float hz = __bfloat162float(__float2bfloat16_rn(v.z));
    float hw = __bfloat162float(__float2bfloat16_rn(v.w));
    uint2 H = make_uint2(pack2(v.x, v.y), pack2(v.z, v.w));
    uint2 L = make_uint2(pack2(v.x - hx, v.y - hy), pack2(v.z - hz, v.w - hw));
    *(uint2*)(hi + off) = H;
    *(uint2*)(lo + off) = L;
}

// ---------------- convert (+ inline int64/int32 detect) --------------------
// g_cnt must be zero on entry: zero-init at load; scan_local re-zeroes it
// after consuming, keeping every graph replay identical.
__global__ void convert_kernel(const void* srcv, const void* dstv) {
    __shared__ int s_ok;
    const unsigned int* p = (const unsigned int*)srcv;
    if (threadIdx.x == 0) s_ok = 1;
    __syncthreads();
    if (threadIdx.x < 64) {
        // int64 with values < 2^31 -> all high words zero
        if (p[2 * threadIdx.x + 1] != 0u) s_ok = 0;
    }
    __syncthreads();
    int idx64 = s_ok;
    int e = blockIdx.x * blockDim.x + threadIdx.x;
    if (e >= NE) return;
    int s, d;
    if (idx64) {
        s = (int)((const long long*)srcv)[e];
        d = (int)((const long long*)dstv)[e];
    } else {
        s = ((const int*)srcv)[e];
        d = ((const int*)dstv)[e];
    }
    g_src[e] = s;
    g_dst[e] = d;
    atomicAdd(&g_cnt[d], 1);
}

// ---------------- CSR build: scan_local + fused(bsum-scan + add) + fill ----
__global__ void scan_local_kernel() {
    __shared__ int s[256];
    int i = blockIdx.x * 256 + threadIdx.x;
    int v = (i < NN) ? g_cnt[i] : 0;
    if (i < NN) g_cnt[i] = 0;          // reset for next replay
    s[threadIdx.x] = v;
    __syncthreads();
#pragma unroll
    for (int off = 1; off < 256; off <<= 1) {
        int t = (threadIdx.x >= off) ? s[threadIdx.x - off] : 0;
        __syncthreads();
        s[threadIdx.x] += t;
        __syncthreads();
    }
    if (i < NN) g_off[i] = s[threadIdx.x] - v;      // exclusive within block
    if (threadIdx.x == 255) g_bsum[blockIdx.x] = s[255];
}

// Each block redundantly scans the 391 block sums in smem, then adds the
// right prefix to its 512 offsets. Replaces scan_bsums + scan_add.
__global__ __launch_bounds__(512) void scan_addb_kernel() {
    __shared__ int s[512], ex[512];
    int t = threadIdx.x;
    int v = (t < NBLK) ? g_bsum[t] : 0;
    s[t] = v;
    __syncthreads();
#pragma unroll
    for (int off = 1; off < 512; off <<= 1) {
        int u = (t >= off) ? s[t - off] : 0;
        __syncthreads();
        s[t] += u;
        __syncthreads();
    }
    ex[t] = s[t] - v;
    __syncthreads();
    int i = blockIdx.x * 512 + t;
    if (i < NN) {
        int o = g_off[i] + ex[i >> 8];
        g_off[i] = o;
        g_cur[i] = o;
    }
}

__global__ void csr_fill_kernel() {
    int e = blockIdx.x * blockDim.x + threadIdx.x;
    if (e >= NE) return;
    int pos = atomicAdd(&g_cur[g_dst[e]], 1);
    g_csr[pos] = g_src[e];
}

// ---------------- aggregation: CSR gather -> bf16 hi/lo split (A cols 128+) -
// Block 0 also zeroes the BN accumulators for this layer (runs before mma).
__global__ __launch_bounds__(256) void aggregate_kernel(const float* __restrict__ h) {
    if (blockIdx.x == 0 && threadIdx.x < 256)
        ((float*)g_bn)[threadIdx.x] = 0.0f;
    int node = (blockIdx.x * blockDim.x + threadIdx.x) >> 5;
    int lane = threadIdx.x & 31;
    if (node >= NN) return;
    int beg = g_off[node];
    int end = (node == NN - 1) ? NE : g_off[node + 1];
    float4 acc = make_float4(0.f, 0.f, 0.f, 0.f);
    int i = beg;
    for (; i + 2 <= end; i += 2) {
        int s0 = g_csr[i];
        int s1 = g_csr[i + 1];
        float4 v0 = ((const float4*)(h + (size_t)s0 * HID))[lane];
        float4 v1 = ((const float4*)(h + (size_t)s1 * HID))[lane];
        acc.x += v0.x + v1.x;
        acc.y += v0.y + v1.y;
        acc.z += v0.z + v1.z;
        acc.w += v0.w + v1.w;
    }
    for (; i < end; i++) {
        int s = g_csr[i];
        float4 v = ((const float4*)(h + (size_t)s * HID))[lane];
        acc.x += v.x; acc.y += v.y; acc.z += v.z; acc.w += v.w;
    }
    float r = 1.0f / (float)max(end - beg, 1);
    acc.x *= r; acc.y *= r; acc.z *= r; acc.w *= r;
    split_store(g_Ahi, g_Alo, (size_t)node * 256 + 128 + lane * 4, acc);
}

// ---------------- prep: x split (blocks < XBLK) + all weight splits --------
#define XBLK 12500                      // NN*32/256 float4 chunks of x
__global__ __launch_bounds__(256) void prep_kernel(
    const float* __restrict__ x,
    const float* __restrict__ ws0, const float* __restrict__ wn0,
    const float* __restrict__ ws1, const float* __restrict__ wn1,
    const float* __restrict__ ws2, const float* __restrict__ wn2)
{
    if (blockIdx.x < XBLK) {
        int idx = blockIdx.x * 256 + threadIdx.x;   // float4 units over NN*128
        float4 v = ((const float4*)x)[idx];
        int row = idx >> 5;
        int c = (idx & 31) * 4;
        split_store(g_Ahi, g_Alo, (size_t)row * 256 + c, v);
    } else {
        int i = (blockIdx.x - XBLK) * 256 + threadIdx.x;  // 0..81919
        const float *ws, *wn;
        int base, cols;
        if (i < 32768)      { ws = ws0; wn = wn0; base = 0;     cols = HID;  }
        else if (i < 65536) { ws = ws1; wn = wn1; base = 32768; cols = HID;  i -= 32768; }
        else                { ws = ws2; wn = wn2; base = 65536; cols = OUTF; i -= 65536; }
        int n = i >> 8;
        int k = i & 255;
        float v = (k < 128) ? ws[k * cols + n] : wn[(k - 128) * cols + n];
        __nv_bfloat16 h = __float2bfloat16_rn(v);
        g_Whi[base + n * 256 + k] = h;
        g_Wlo[base + n * 256 + k] = __float2bfloat16_rn(v - __bfloat162float(h));
    }
}

// ---------------- mma.sync GEMM: D = A(128x256) @ W^T, bf16x2 split ---------
// Block 256 thr (8 warps), tile 128xCOLS, KC=32 double-buffered cp.async.
// Warp grid: COLS=128 -> 4Mx2N; COLS=64 -> 8Mx1N (log_softmax intra-warp).
// MODE 0: out = D + bias, BN sum/sumsq accumulated into g_bn (smem reduce).
// MODE 1: out = log_softmax(D + bias) rowwise.
template<int COLS, int MODE>
__global__ __launch_bounds__(256) void sage_mma(
    const float* __restrict__ bias, float* __restrict__ outp,
    const __nv_bfloat16* __restrict__ whi, const __nv_bfloat16* __restrict__ wlo)
{
    extern __shared__ __align__(1024) char smem[];
    constexpr int BB  = COLS * 128;          // B stage bytes
    constexpr int A1o = 16384;
    constexpr int B0o = 32768;
    constexpr int B1o = 32768 + BB;
    constexpr int NWN = (COLS == 128) ? 2 : 1;   // warps along N
    constexpr int NWM = 8 / NWN;                 // warps along M
    constexpr int MI  = 128 / (NWM * 16);        // m16 steps per warp (2 or 1)
    constexpr int WARP_N = COLS / NWN;           // 64
    constexpr int NI  = WARP_N / 8;              // 8

    const int tid  = threadIdx.x;
    const int wid  = tid >> 5;
    const int lane = tid & 31;
    const int wm   = wid / NWN;
    const int wn   = wid % NWN;
    const int row0 = blockIdx.x * 128;
    const uint32_t sb = smem_u32(smem);

    const int arow = wm * (MI * 16) + (lane & 15);   // + mi*16
    const int acb  = (lane >> 4) * 16;
    const int brow = wn * WARP_N + (lane & 7);       // + ni*8
    const int bcb  = ((lane >> 3) & 1) * 16;

    float acc[MI][NI][4];
#pragma unroll
    for (int mi = 0; mi < MI; mi++)
#pragma unroll
        for (int ni = 0; ni < NI; ni++)
#pragma unroll
            for (int q = 0; q < 4; q++) acc[mi][ni][q] = 0.0f;

    auto load_stage = [&](int ks, int buf) {
        uint32_t Ab = sb + (buf ? A1o : 0);
        uint32_t Bb = sb + (buf ? B1o : B0o);
#pragma unroll
        for (int i = 0; i < 4; i++) {                // A: 1024 16B chunks
            int u = tid + i * 256;
            int r = u >> 3, c = u & 7;
            int rowg = min(row0 + r, NN - 1);
            const __nv_bfloat16* g = (c < 4 ? g_Ahi : g_Alo)
                                   + (size_t)rowg * 256 + ks * 32 + (c & 3) * 8;
            cp16(Ab + sw128(r * 128 + c * 16), g);
        }
#pragma unroll
        for (int i = 0; i < COLS / 32; i++) {        // B: COLS*8 chunks
            int u = tid + i * 256;
            int n = u >> 3, c = u & 7;
            const __nv_bfloat16* g = (c < 4 ? whi : wlo)
                                   + (size_t)n * 256 + ks * 32 + (c & 3) * 8;
            cp16(Bb + sw128(n * 128 + c * 16), g);
        }
    };

    auto compute_stage = [&](int buf) {
        uint32_t Ab = sb + (buf ? A1o : 0);
        uint32_t Bb = sb + (buf ? B1o : B0o);
#pragma unroll
        for (int kk = 0; kk < 2; kk++) {             // two k16 steps per stage
            uint32_t bh[NI][2], bl[NI][2];
#pragma unroll
            for (int ni = 0; ni < NI; ni++) {
                uint32_t off = (uint32_t)(brow + ni * 8) * 128 + kk * 32 + bcb;
                ldm_x2(bh[ni], Bb + sw128(off));
                ldm_x2(bl[ni], Bb + sw128(off + 64));
            }
#pragma unroll
            for (int mi = 0; mi < MI; mi++) {
                uint32_t ah[4], al[4];
                uint32_t off = (uint32_t)(arow + mi * 16) * 128 + kk * 32 + acb;
                ldm_x4(ah, Ab + sw128(off));
                ldm_x4(al, Ab + sw128(off + 64));
#pragma unroll
                for (int ni = 0; ni < NI; ni++) {
                    mma_bf16(acc[mi][ni], ah, bh[ni]);   // hi*hi
                    mma_bf16(acc[mi][ni], ah, bl[ni]);   // hi*lo
                    mma_bf16(acc[mi][ni], al, bh[ni]);   // lo*hi
                }
            }
        }
    };

    load_stage(0, 0);
    cp_commit();
    for (int ks = 0; ks < 8; ks++) {
        if (ks < 7) {
            load_stage(ks + 1, (ks + 1) & 1);
            cp_commit();
            cp_wait<1>();
        } else {
            cp_wait<0>();
        }
        __syncthreads();
        compute_stage(ks & 1);
        __syncthreads();
    }

    // ---- epilogue: add bias into acc ----
#pragma unroll
    for (int mi = 0; mi < MI; mi++)
#pragma unroll
        for (int ni = 0; ni < NI; ni++) {
            int c = wn * WARP_N + ni * 8 + (lane & 3) * 2;
            float b0 = __ldg(bias + c), b1 = __ldg(bias + c + 1);
            acc[mi][ni][0] += b0; acc[mi][ni][1] += b1;
            acc[mi][ni][2] += b0; acc[mi][ni][3] += b1;
        }

    const int r_base = row0 + wm * (MI * 16) + (lane >> 2);

    if (MODE == 0) {
        // store + per-thread BN partials (row-guarded)
        float vs[2 * NI], vq[2 * NI];
#pragma unroll
        for (int j = 0; j < 2 * NI; j++) { vs[j] = 0.f; vq[j] = 0.f; }
#pragma unroll
        for (int mi = 0; mi < MI; mi++) {
            int rA = r_base + mi * 16;
            int rB = rA + 8;
            bool gA = rA < NN, gB = rB < NN;
#pragma unroll
            for (int ni = 0; ni < NI; ni++) {
                int c = wn * WARP_N + ni * 8 + (lane & 3) * 2;
                if (gA) {
                    float2 o = make_float2(acc[mi][ni][0], acc[mi][ni][1]);
                    *(float2*)(outp + (size_t)rA * COLS + c) = o;
                    vs[2 * ni] += o.x;     vq[2 * ni] += o.x * o.x;
                    vs[2 * ni + 1] += o.y; vq[2 * ni + 1] += o.y * o.y;
                }
                if (gB) {
                    float2 o = make_float2(acc[mi][ni][2], acc[mi][ni][3]);
                    *(float2*)(outp + (size_t)rB * COLS + c) = o;
                    vs[2 * ni] += o.x;     vq[2 * ni] += o.x * o.x;
                    vs[2 * ni + 1] += o.y; vq[2 * ni + 1] += o.y * o.y;
                }
            }
        }
        // block reduce in smem (stage buffers are dead now), then global atomics
        float* sred = (float*)smem;      // [0..127]=sum, [128..255]=sumsq
        sred[tid] = 0.0f;
        __syncthreads();
#pragma unroll
        for (int ni = 0; ni < NI; ni++) {
            int c = wn * WARP_N + ni * 8 + (lane & 3) * 2;
            atomicAdd(&sred[c],           vs[2 * ni]);
            atomicAdd(&sred[c + 1],       vs[2 * ni + 1]);
            atomicAdd(&sred[128 + c],     vq[2 * ni]);
            atomicAdd(&sred[128 + c + 1], vq[2 * ni + 1]);
        }
        __syncthreads();
        if (tid < 256) atomicAdd(&((float*)g_bn)[tid], sred[tid]);
    } else {
        // log_softmax over COLS=64: one warp owns all 64 cols of its rows.
#pragma unroll
        for (int mi = 0; mi < MI; mi++) {
            float mA = -INFINITY, mB = -INFINITY;
#pragma unroll
            for (int ni = 0; ni < NI; ni++) {
                mA = fmaxf(mA, fmaxf(acc[mi][ni][0], acc[mi][ni][1]));
                mB = fmaxf(mB, fmaxf(acc[mi][ni][2], acc[mi][ni][3]));
            }
#pragma unroll
            for (int off = 1; off <= 2; off <<= 1) {
                mA = fmaxf(mA, __shfl_xor_sync(0xffffffffu, mA, off));
                mB = fmaxf(mB, __shfl_xor_sync(0xffffffffu, mB, off));
            }
            float sA = 0.f, sB = 0.f;
#pragma unroll
            for (int ni = 0; ni < NI; ni++) {
                sA += expf(acc[mi][ni][0] - mA) + expf(acc[mi][ni][1] - mA);
                sB += expf(acc[mi][ni][2] - mB) + expf(acc[mi][ni][3] - mB);
            }
#pragma unroll
            for (int off = 1; off <= 2; off <<= 1) {
                sA += __shfl_xor_sync(0xffffffffu, sA, off);
                sB += __shfl_xor_sync(0xffffffffu, sB, off);
            }
            float lseA = mA + logf(sA);
            float lseB = mB + logf(sB);
            int rA = r_base + mi * 16;
            int rB = rA + 8;
#pragma unroll
            for (int ni = 0; ni < NI; ni++) {
                int c = wn * WARP_N + ni * 8 + (lane & 3) * 2;
                if (rA < NN) {
                    float2 o = make_float2(acc[mi][ni][0] - lseA, acc[mi][ni][1] - lseA);
                    *(float2*)(outp + (size_t)rA * COLS + c) = o;
                }
                if (rB < NN) {
                    float2 o = make_float2(acc[mi][ni][2] - lseB, acc[mi][ni][3] - lseB);
                    *(float2*)(outp + (size_t)rB * COLS + c) = o;
                }
            }
        }
    }
}

// ---------------- BN finalize (inline) + apply + ReLU + split --------------
__global__ __launch_bounds__(256) void bn_apply_kernel(
    const float* __restrict__ gamma, const float* __restrict__ beta,
    const float* __restrict__ in, float* __restrict__ outp)
{
    __shared__ float sc[HID], sh[HID];
    if (threadIdx.x < HID) {
        int c = threadIdx.x;
        float s  = g_bn[0][c];
        float sq = g_bn[1][c];
        float mu  = s / (float)NN;
        float var = sq / (float)NN - mu * mu;
        float scv = gamma[c] * rsqrtf(var + 1e-5f);
        sc[c] = scv;
        sh[c] = beta[c] - mu * scv;
    }
    __syncthreads();
    int idx = blockIdx.x * blockDim.x + threadIdx.x;   // float4 units
    if (idx >= NN * 32) return;
    float4 v = ((const float4*)in)[idx];
    int row = idx >> 5;
    int c = (idx & 31) * 4;
    float4 o;
    o.x = fmaxf(fmaf(v.x, sc[c + 0], sh[c + 0]), 0.0f);
    o.y = fmaxf(fmaf(v.y, sc[c + 1], sh[c + 1]), 0.0f);
    o.z = fmaxf(fmaf(v.z, sc[c + 2], sh[c + 2]), 0.0f);
    o.w = fmaxf(fmaf(v.w, sc[c + 3], sh[c + 3]), 0.0f);
    ((float4*)outp)[idx] = o;
    split_store(g_Ahi, g_Alo, (size_t)row * 256 + c, o);
}

// ---------------- launch ----------------------------------------------------
extern "C" void kernel_launch(void* const* d_in, const int* in_sizes, int n_in,
                              void* d_out, int out_size) {
    const float* x   = (const float*)d_in[0];
    const void*  src = d_in[1];
    const void*  dst = d_in[2];
    const float* ws0 = (const float*)d_in[3];
    const float* wn0 = (const float*)d_in[4];
    const float* b0  = (const float*)d_in[5];
    const float* ws1 = (const float*)d_in[6];
    const float* wn1 = (const float*)d_in[7];
    const float* b1  = (const float*)d_in[8];
    const float* ws2 = (const float*)d_in[9];
    const float* wn2 = (const float*)d_in[10];
    const float* b2  = (const float*)d_in[11];
    const float* gamma0 = (const float*)d_in[12];
    const float* beta0  = (const float*)d_in[13];
    const float* gamma1 = (const float*)d_in[14];
    const float* beta1  = (const float*)d_in[15];
    float* out = (float*)d_out;

    void *hAp, *hBp, *whip, *wlop;
    cudaGetSymbolAddress(&hAp, g_hA);
    cudaGetSymbolAddress(&hBp, g_hB);
    cudaGetSymbolAddress(&whip, g_Whi);
    cudaGetSymbolAddress(&wlop, g_Wlo);
    float* hA = (float*)hAp;
    float* hB = (float*)hBp;
    const __nv_bfloat16* whi = (const __nv_bfloat16*)whip;
    const __nv_bfloat16* wlo = (const __nv_bfloat16*)wlop;

    const int SMEM128 = 2 * 16384 + 2 * 128 * 128;   // 65536
    const int SMEM64  = 2 * 16384 + 2 * 64 * 128;    // 49152
    cudaFuncSetAttribute(sage_mma<128, 0>, cudaFuncAttributeMaxDynamicSharedMemorySize, SMEM128);
    cudaFuncSetAttribute(sage_mma<64, 1>,  cudaFuncAttributeMaxDynamicSharedMemorySize, SMEM64);

    const int egrid = (NE + 255) / 256;              // 6250
    const int mgrid = (NN + 127) / 128;              // 782
    const int agrid = (NN * 32 + 255) / 256;         // 12500
    const int ngrid = (NN * 32 + 255) / 256;         // warp-per-node: 12500
    const int sgrid = (NN + 511) / 512;              // 196

    // ---- CSR build (4 launches) then layer-0 aggregate in the ncu slot ----
    convert_kernel<<<egrid, 256>>>(src, dst);                    // 1
    scan_local_kernel<<<NBLK, 256>>>();                          // 2
    scan_addb_kernel<<<sgrid, 512>>>();                          // 3
    csr_fill_kernel<<<egrid, 256>>>();                           // 4

    // ---- layer 0 ----
    aggregate_kernel<<<ngrid, 256>>>(x);                         // 5  <- profiled
    prep_kernel<<<XBLK + 320, 256>>>(x, ws0, wn0, ws1, wn1, ws2, wn2);  // 6
    sage_mma<128, 0><<<mgrid, 256, SMEM128>>>(b0, hA, whi, wlo);        // 7
    bn_apply_kernel<<<agrid, 256>>>(gamma0, beta0, hA, hB);             // 8

    // ---- layer 1 ----
    aggregate_kernel<<<ngrid, 256>>>(hB);                               // 9
    sage_mma<128, 0><<<mgrid, 256, SMEM128>>>(b1, hA, whi + 32768, wlo + 32768); // 10
    bn_apply_kernel<<<agrid, 256>>>(gamma1, beta1, hA, hB);             // 11

    // ---- layer 2 (+ fused log_softmax) ----
    aggregate_kernel<<<ngrid, 256>>>(hB);                               // 12
    sage_mma<64, 1><<<mgrid, 256, SMEM64>>>(b2, out, whi + 65536, wlo + 65536);  // 13
}

// round 11
// speedup vs baseline: 1.7634x; 1.0375x over previous
#include <cuda_runtime.h>
#include <cuda_bf16.h>
#include <cuda_fp16.h>
#include <math.h>
#include <stdint.h>

#define NN 100000
#define NE 1600000
#define HID 128
#define OUTF 64
#define NBLK ((NN + 255) / 256)   // 391 scan_local blocks

// ---------------- scratch (static device globals; no allocations) ----------
__device__ int   g_src[NE];
__device__ int   g_dst[NE];
__device__ int   g_cnt[NN];
__device__ int   g_off[NN];
__device__ int   g_cur[NN];
__device__ int   g_bsum[512];
__device__ int   g_csr[NE];
__device__ __align__(16) float g_hA[NN * HID];            // GEMM linear out
__device__ __align__(16) __half g_h16[NN * HID];          // fp16 gather source
__device__ __align__(16) __nv_bfloat16 g_Ahi[NN * 256];   // A = [h | agg] hi split
__device__ __align__(16) __nv_bfloat16 g_Alo[NN * 256];   // A lo split
__device__ __align__(16) __nv_bfloat16 g_Whi[320 * 256];  // W^T hi, layers at 0/32768/65536
__device__ __align__(16) __nv_bfloat16 g_Wlo[320 * 256];  // W^T lo
__device__ __align__(16) float g_bn[2][HID];              // [0]=sum [1]=sumsq

// ---------------- ptx helpers (all sm_80-era, no arch-'a' features) --------
__device__ __forceinline__ uint32_t smem_u32(const void* p) {
    uint32_t a;
    asm("{ .reg .u64 t; cvta.to.shared.u64 t, %1; cvt.u32.u64 %0, t; }"
        : "=r"(a) : "l"(p));
    return a;
}
__device__ __forceinline__ uint32_t sw128(uint32_t b) { return b ^ ((b >> 3) & 0x70); }

__device__ __forceinline__ void cp16(uint32_t sdst, const void* gsrc) {
    asm volatile("cp.async.cg.shared.global [%0], [%1], 16;"
                 :: "r"(sdst), "l"(gsrc) : "memory");
}
__device__ __forceinline__ void cp_commit() {
    asm volatile("cp.async.commit_group;" ::: "memory");
}
template<int W> __device__ __forceinline__ void cp_wait() {
    asm volatile("cp.async.wait_group %0;" :: "n"(W) : "memory");
}
__device__ __forceinline__ void ldm_x4(uint32_t* r, uint32_t a) {
    asm volatile("ldmatrix.sync.aligned.m8n8.x4.shared.b16 {%0,%1,%2,%3}, [%4];"
                 : "=r"(r[0]), "=r"(r[1]), "=r"(r[2]), "=r"(r[3]) : "r"(a));
}
__device__ __forceinline__ void ldm_x2(uint32_t* r, uint32_t a) {
    asm volatile("ldmatrix.sync.aligned.m8n8.x2.shared.b16 {%0,%1}, [%2];"
                 : "=r"(r[0]), "=r"(r[1]) : "r"(a));
}
__device__ __forceinline__ void mma_bf16(float* d, const uint32_t* a, const uint32_t* b) {
    asm volatile("mma.sync.aligned.m16n8k16.row.col.f32.bf16.bf16.f32 "
                 "{%0,%1,%2,%3}, {%4,%5,%6,%7}, {%8,%9}, {%0,%1,%2,%3};"
                 : "+f"(d[0]), "+f"(d[1]), "+f"(d[2]), "+f"(d[3])
                 : "r"(a[0]), "r"(a[1]), "r"(a[2]), "r"(a[3]),
                   "r"(b[0]), "r"(b[1]));
}
__device__ __forceinline__ uint32_t pack2(float a, float b) {
    __nv_bfloat162 t = __floats2bfloat162_rn(a, b);
    return *(uint32_t*)&t;
}
__device__ __forceinline__ void split_store(__nv_bfloat16* hi, __nv_bfloat16* lo,
                                            size_t off, float4 v) {
    float hx = __bfloat162float(__float2bfloat16_rn(v.x));
    float hy = __bfloat162float(__float2bfloat16_rn(v.y));
    float hz = __bfloat162float(__float2bfloat16_rn(v.z));
    float hw = __bfloat162float(__float2bfloat16_rn(v.w));
    uint2 H = make_uint2(pack2(v.x, v.y), pack2(v.z, v.w));
    uint2 L = make_uint2(pack2(v.x - hx, v.y - hy), pack2(v.z - hz, v.w - hw));
    *(uint2*)(hi + off) = H;
    *(uint2*)(lo + off) = L;
}
__device__ __forceinline__ uint2 pack_h16(float4 v) {
    __half2 a = __floats2half2_rn(v.x, v.y);
    __half2 b = __floats2half2_rn(v.z, v.w);
    return make_uint2(*(uint32_t*)&a, *(uint32_t*)&b);
}

// ---------------- convert (+ inline int64/int32 detect) --------------------
// g_cnt must be zero on entry: zero-init at load; scan_local re-zeroes it
// after consuming, keeping every graph replay identical.
__global__ void convert_kernel(const void* srcv, const void* dstv) {
    __shared__ int s_ok;
    const unsigned int* p = (const unsigned int*)srcv;
    if (threadIdx.x == 0) s_ok = 1;
    __syncthreads();
    if (threadIdx.x < 64) {
        // int64 with values < 2^31 -> all high words zero
        if (p[2 * threadIdx.x + 1] != 0u) s_ok = 0;
    }
    __syncthreads();
    int idx64 = s_ok;
    int e = blockIdx.x * blockDim.x + threadIdx.x;
    if (e >= NE) return;
    int s, d;
    if (idx64) {
        s = (int)((const long long*)srcv)[e];
        d = (int)((const long long*)dstv)[e];
    } else {
        s = ((const int*)srcv)[e];
        d = ((const int*)dstv)[e];
    }
    g_src[e] = s;
    g_dst[e] = d;
    atomicAdd(&g_cnt[d], 1);
}

// ---------------- CSR build: scan_local + fused(bsum-scan + add) + fill ----
__global__ void scan_local_kernel() {
    __shared__ int s[256];
    int i = blockIdx.x * 256 + threadIdx.x;
    int v = (i < NN) ? g_cnt[i] : 0;
    if (i < NN) g_cnt[i] = 0;          // reset for next replay
    s[threadIdx.x] = v;
    __syncthreads();
#pragma unroll
    for (int off = 1; off < 256; off <<= 1) {
        int t = (threadIdx.x >= off) ? s[threadIdx.x - off] : 0;
        __syncthreads();
        s[threadIdx.x] += t;
        __syncthreads();
    }
    if (i < NN) g_off[i] = s[threadIdx.x] - v;      // exclusive within block
    if (threadIdx.x == 255) g_bsum[blockIdx.x] = s[255];
}

// Each block redundantly scans the 391 block sums in smem, then adds the
// right prefix to its 512 offsets. Replaces scan_bsums + scan_add.
__global__ __launch_bounds__(512) void scan_addb_kernel() {
    __shared__ int s[512], ex[512];
    int t = threadIdx.x;
    int v = (t < NBLK) ? g_bsum[t] : 0;
    s[t] = v;
    __syncthreads();
#pragma unroll
    for (int off = 1; off < 512; off <<= 1) {
        int u = (t >= off) ? s[t - off] : 0;
        __syncthreads();
        s[t] += u;
        __syncthreads();
    }
    ex[t] = s[t] - v;
    __syncthreads();
    int i = blockIdx.x * 512 + t;
    if (i < NN) {
        int o = g_off[i] + ex[i >> 8];
        g_off[i] = o;
        g_cur[i] = o;
    }
}

__global__ void csr_fill_kernel() {
    int e = blockIdx.x * blockDim.x + threadIdx.x;
    if (e >= NE) return;
    int pos = atomicAdd(&g_cur[g_dst[e]], 1);
    g_csr[pos] = g_src[e];
}

// ---------------- prep: x split + x fp16 (blocks < XBLK) + weight splits ---
#define XBLK 12500                      // NN*32/256 float4 chunks of x
__global__ __launch_bounds__(256) void prep_kernel(
    const float* __restrict__ x,
    const float* __restrict__ ws0, const float* __restrict__ wn0,
    const float* __restrict__ ws1, const float* __restrict__ wn1,
    const float* __restrict__ ws2, const float* __restrict__ wn2)
{
    if (blockIdx.x < XBLK) {
        int idx = blockIdx.x * 256 + threadIdx.x;   // float4 units over NN*128
        float4 v = ((const float4*)x)[idx];
        int row = idx >> 5;
        int c = (idx & 31) * 4;
        split_store(g_Ahi, g_Alo, (size_t)row * 256 + c, v);
        *(uint2*)(g_h16 + (size_t)row * HID + c) = pack_h16(v);
    } else {
        int i = (blockIdx.x - XBLK) * 256 + threadIdx.x;  // 0..81919
        const float *ws, *wn;
        int base, cols;
        if (i < 32768)      { ws = ws0; wn = wn0; base = 0;     cols = HID;  }
        else if (i < 65536) { ws = ws1; wn = wn1; base = 32768; cols = HID;  i -= 32768; }
        else                { ws = ws2; wn = wn2; base = 65536; cols = OUTF; i -= 65536; }
        int n = i >> 8;
        int k = i & 255;
        float v = (k < 128) ? ws[k * cols + n] : wn[(k - 128) * cols + n];
        __nv_bfloat16 h = __float2bfloat16_rn(v);
        g_Whi[base + n * 256 + k] = h;
        g_Wlo[base + n * 256 + k] = __float2bfloat16_rn(v - __bfloat162float(h));
    }
}

// ---------------- aggregation: CSR gather (fp16 rows) -> bf16 hi/lo split --
// Row = 128 fp16 = 256B; each lane loads uint2 (4 halves). fp32 accumulate.
// Block 0 also zeroes the BN accumulators for this layer (runs before mma).
__global__ __launch_bounds__(256) void aggregate_kernel() {
    if (blockIdx.x == 0 && threadIdx.x < 256)
        ((float*)g_bn)[threadIdx.x] = 0.0f;
    int node = (blockIdx.x * blockDim.x + threadIdx.x) >> 5;
    int lane = threadIdx.x & 31;
    if (node >= NN) return;
    int beg = g_off[node];
    int end = (node == NN - 1) ? NE : g_off[node + 1];
    float4 acc = make_float4(0.f, 0.f, 0.f, 0.f);
    int i = beg;
    for (; i + 2 <= end; i += 2) {
        int s0 = g_csr[i];
        int s1 = g_csr[i + 1];
        uint2 u0 = ((const uint2*)(g_h16 + (size_t)s0 * HID))[lane];
        uint2 u1 = ((const uint2*)(g_h16 + (size_t)s1 * HID))[lane];
        float2 a0 = __half22float2(*(__half2*)&u0.x);
        float2 b0 = __half22float2(*(__half2*)&u0.y);
        float2 a1 = __half22float2(*(__half2*)&u1.x);
        float2 b1 = __half22float2(*(__half2*)&u1.y);
        acc.x += a0.x + a1.x;
        acc.y += a0.y + a1.y;
        acc.z += b0.x + b1.x;
        acc.w += b0.y + b1.y;
    }
    for (; i < end; i++) {
        int s = g_csr[i];
        uint2 u = ((const uint2*)(g_h16 + (size_t)s * HID))[lane];
        float2 a = __half22float2(*(__half2*)&u.x);
        float2 b = __half22float2(*(__half2*)&u.y);
        acc.x += a.x; acc.y += a.y; acc.z += b.x; acc.w += b.y;
    }
    float r = 1.0f / (float)max(end - beg, 1);
    acc.x *= r; acc.y *= r; acc.z *= r; acc.w *= r;
    split_store(g_Ahi, g_Alo, (size_t)node * 256 + 128 + lane * 4, acc);
}

// ---------------- mma.sync GEMM: D = A(128x256) @ W^T, bf16x2 split ---------
// Block 256 thr (8 warps), tile 128xCOLS, KC=32 double-buffered cp.async.
// Warp grid: COLS=128 -> 4Mx2N; COLS=64 -> 8Mx1N (log_softmax intra-warp).
// MODE 0: out = D + bias, BN sum/sumsq accumulated into g_bn (smem reduce).
// MODE 1: out = log_softmax(D + bias) rowwise.
template<int COLS, int MODE>
__global__ __launch_bounds__(256) void sage_mma(
    const float* __restrict__ bias, float* __restrict__ outp,
    const __nv_bfloat16* __restrict__ whi, const __nv_bfloat16* __restrict__ wlo)
{
    extern __shared__ __align__(1024) char smem[];
    constexpr int BB  = COLS * 128;          // B stage bytes
    constexpr int A1o = 16384;
    constexpr int B0o = 32768;
    constexpr int B1o = 32768 + BB;
    constexpr int NWN = (COLS == 128) ? 2 : 1;   // warps along N
    constexpr int NWM = 8 / NWN;                 // warps along M
    constexpr int MI  = 128 / (NWM * 16);        // m16 steps per warp (2 or 1)
    constexpr int WARP_N = COLS / NWN;           // 64
    constexpr int NI  = WARP_N / 8;              // 8

    const int tid  = threadIdx.x;
    const int wid  = tid >> 5;
    const int lane = tid & 31;
    const int wm   = wid / NWN;
    const int wn   = wid % NWN;
    const int row0 = blockIdx.x * 128;
    const uint32_t sb = smem_u32(smem);

    const int arow = wm * (MI * 16) + (lane & 15);   // + mi*16
    const int acb  = (lane >> 4) * 16;
    const int brow = wn * WARP_N + (lane & 7);       // + ni*8
    const int bcb  = ((lane >> 3) & 1) * 16;

    float acc[MI][NI][4];
#pragma unroll
    for (int mi = 0; mi < MI; mi++)
#pragma unroll
        for (int ni = 0; ni < NI; ni++)
#pragma unroll
            for (int q = 0; q < 4; q++) acc[mi][ni][q] = 0.0f;

    auto load_stage = [&](int ks, int buf) {
        uint32_t Ab = sb + (buf ? A1o : 0);
        uint32_t Bb = sb + (buf ? B1o : B0o);
#pragma unroll
        for (int i = 0; i < 4; i++) {                // A: 1024 16B chunks
            int u = tid + i * 256;
            int r = u >> 3, c = u & 7;
            int rowg = min(row0 + r, NN - 1);
            const __nv_bfloat16* g = (c < 4 ? g_Ahi : g_Alo)
                                   + (size_t)rowg * 256 + ks * 32 + (c & 3) * 8;
            cp16(Ab + sw128(r * 128 + c * 16), g);
        }
#pragma unroll
        for (int i = 0; i < COLS / 32; i++) {        // B: COLS*8 chunks
            int u = tid + i * 256;
            int n = u >> 3, c = u & 7;
            const __nv_bfloat16* g = (c < 4 ? whi : wlo)
                                   + (size_t)n * 256 + ks * 32 + (c & 3) * 8;
            cp16(Bb + sw128(n * 128 + c * 16), g);
        }
    };

    auto compute_stage = [&](int buf) {
        uint32_t Ab = sb + (buf ? A1o : 0);
        uint32_t Bb = sb + (buf ? B1o : B0o);
#pragma unroll
        for (int kk = 0; kk < 2; kk++) {             // two k16 steps per stage
            uint32_t bh[NI][2], bl[NI][2];
#pragma unroll
            for (int ni = 0; ni < NI; ni++) {
                uint32_t off = (uint32_t)(brow + ni * 8) * 128 + kk * 32 + bcb;
                ldm_x2(bh[ni], Bb + sw128(off));
                ldm_x2(bl[ni], Bb + sw128(off + 64));
            }
#pragma unroll
            for (int mi = 0; mi < MI; mi++) {
                uint32_t ah[4], al[4];
                uint32_t off = (uint32_t)(arow + mi * 16) * 128 + kk * 32 + acb;
                ldm_x4(ah, Ab + sw128(off));
                ldm_x4(al, Ab + sw128(off + 64));
#pragma unroll
                for (int ni = 0; ni < NI; ni++) {
                    mma_bf16(acc[mi][ni], ah, bh[ni]);   // hi*hi
                    mma_bf16(acc[mi][ni], ah, bl[ni]);   // hi*lo
                    mma_bf16(acc[mi][ni], al, bh[ni]);   // lo*hi
                }
            }
        }
    };

    load_stage(0, 0);
    cp_commit();
    for (int ks = 0; ks < 8; ks++) {
        if (ks < 7) {
            load_stage(ks + 1, (ks + 1) & 1);
            cp_commit();
            cp_wait<1>();
        } else {
            cp_wait<0>();
        }
        __syncthreads();
        compute_stage(ks & 1);
        __syncthreads();
    }

    // ---- epilogue: add bias into acc ----
#pragma unroll
    for (int mi = 0; mi < MI; mi++)
#pragma unroll
        for (int ni = 0; ni < NI; ni++) {
            int c = wn * WARP_N + ni * 8 + (lane & 3) * 2;
            float b0 = __ldg(bias + c), b1 = __ldg(bias + c + 1);
            acc[mi][ni][0] += b0; acc[mi][ni][1] += b1;
            acc[mi][ni][2] += b0; acc[mi][ni][3] += b1;
        }

    const int r_base = row0 + wm * (MI * 16) + (lane >> 2);

    if (MODE == 0) {
        // store + per-thread BN partials (row-guarded)
        float vs[2 * NI], vq[2 * NI];
#pragma unroll
        for (int j = 0; j < 2 * NI; j++) { vs[j] = 0.f; vq[j] = 0.f; }
#pragma unroll
        for (int mi = 0; mi < MI; mi++) {
            int rA = r_base + mi * 16;
            int rB = rA + 8;
            bool gA = rA < NN, gB = rB < NN;
#pragma unroll
            for (int ni = 0; ni < NI; ni++) {
                int c = wn * WARP_N + ni * 8 + (lane & 3) * 2;
                if (gA) {
                    float2 o = make_float2(acc[mi][ni][0], acc[mi][ni][1]);
                    *(float2*)(outp + (size_t)rA * COLS + c) = o;
                    vs[2 * ni] += o.x;     vq[2 * ni] += o.x * o.x;
                    vs[2 * ni + 1] += o.y; vq[2 * ni + 1] += o.y * o.y;
                }
                if (gB) {
                    float2 o = make_float2(acc[mi][ni][2], acc[mi][ni][3]);
                    *(float2*)(outp + (size_t)rB * COLS + c) = o;
                    vs[2 * ni] += o.x;     vq[2 * ni] += o.x * o.x;
                    vs[2 * ni + 1] += o.y; vq[2 * ni + 1] += o.y * o.y;
                }
            }
        }
        // block reduce in smem (stage buffers are dead now), then global atomics
        float* sred = (float*)smem;      // [0..127]=sum, [128..255]=sumsq
        sred[tid] = 0.0f;
        __syncthreads();
#pragma unroll
        for (int ni = 0; ni < NI; ni++) {
            int c = wn * WARP_N + ni * 8 + (lane & 3) * 2;
            atomicAdd(&sred[c],           vs[2 * ni]);
            atomicAdd(&sred[c + 1],       vs[2 * ni + 1]);
            atomicAdd(&sred[128 + c],     vq[2 * ni]);
            atomicAdd(&sred[128 + c + 1], vq[2 * ni + 1]);
        }
        __syncthreads();
        if (tid < 256) atomicAdd(&((float*)g_bn)[tid], sred[tid]);
    } else {
        // log_softmax over COLS=64: one warp owns all 64 cols of its rows.
#pragma unroll
        for (int mi = 0; mi < MI; mi++) {
            float mA = -INFINITY, mB = -INFINITY;
#pragma unroll
            for (int ni = 0; ni < NI; ni++) {
                mA = fmaxf(mA, fmaxf(acc[mi][ni][0], acc[mi][ni][1]));
                mB = fmaxf(mB, fmaxf(acc[mi][ni][2], acc[mi][ni][3]));
            }
#pragma unroll
            for (int off = 1; off <= 2; off <<= 1) {
                mA = fmaxf(mA, __shfl_xor_sync(0xffffffffu, mA, off));
                mB = fmaxf(mB, __shfl_xor_sync(0xffffffffu, mB, off));
            }
            float sA = 0.f, sB = 0.f;
#pragma unroll
            for (int ni = 0; ni < NI; ni++) {
                sA += expf(acc[mi][ni][0] - mA) + expf(acc[mi][ni][1] - mA);
                sB += expf(acc[mi][ni][2] - mB) + expf(acc[mi][ni][3] - mB);
            }
#pragma unroll
            for (int off = 1; off <= 2; off <<= 1) {
                sA += __shfl_xor_sync(0xffffffffu, sA, off);
                sB += __shfl_xor_sync(0xffffffffu, sB, off);
            }
            float lseA = mA + logf(sA);
            float lseB = mB + logf(sB);
            int rA = r_base + mi * 16;
            int rB = rA + 8;
#pragma unroll
            for (int ni = 0; ni < NI; ni++) {
                int c = wn * WARP_N + ni * 8 + (lane & 3) * 2;
                if (rA < NN) {
                    float2 o = make_float2(acc[mi][ni][0] - lseA, acc[mi][ni][1] - lseA);
                    *(float2*)(outp + (size_t)rA * COLS + c) = o;
                }
                if (rB < NN) {
                    float2 o = make_float2(acc[mi][ni][2] - lseB, acc[mi][ni][3] - lseB);
                    *(float2*)(outp + (size_t)rB * COLS + c) = o;
                }
            }
        }
    }
}

// ---------------- BN finalize (inline) + apply + ReLU + fp16 + split -------
__global__ __launch_bounds__(256) void bn_apply_kernel(
    const float* __restrict__ gamma, const float* __restrict__ beta,
    const float* __restrict__ in)
{
    __shared__ float sc[HID], sh[HID];
    if (threadIdx.x < HID) {
        int c = threadIdx.x;
        float s  = g_bn[0][c];
        float sq = g_bn[1][c];
        float mu  = s / (float)NN;
        float var = sq / (float)NN - mu * mu;
        float scv = gamma[c] * rsqrtf(var + 1e-5f);
        sc[c] = scv;
        sh[c] = beta[c] - mu * scv;
    }
    __syncthreads();
    int idx = blockIdx.x * blockDim.x + threadIdx.x;   // float4 units
    if (idx >= NN * 32) return;
    float4 v = ((const float4*)in)[idx];
    int row = idx >> 5;
    int c = (idx & 31) * 4;
    float4 o;
    o.x = fmaxf(fmaf(v.x, sc[c + 0], sh[c + 0]), 0.0f);
    o.y = fmaxf(fmaf(v.y, sc[c + 1], sh[c + 1]), 0.0f);
    o.z = fmaxf(fmaf(v.z, sc[c + 2], sh[c + 2]), 0.0f);
    o.w = fmaxf(fmaf(v.w, sc[c + 3], sh[c + 3]), 0.0f);
    *(uint2*)(g_h16 + (size_t)row * HID + c) = pack_h16(o);
    split_store(g_Ahi, g_Alo, (size_t)row * 256 + c, o);
}

// ---------------- launch ----------------------------------------------------
extern "C" void kernel_launch(void* const* d_in, const int* in_sizes, int n_in,
                              void* d_out, int out_size) {
    const float* x   = (const float*)d_in[0];
    const void*  src = d_in[1];
    const void*  dst = d_in[2];
    const float* ws0 = (const float*)d_in[3];
    const float* wn0 = (const float*)d_in[4];
    const float* b0  = (const float*)d_in[5];
    const float* ws1 = (const float*)d_in[6];
    const float* wn1 = (const float*)d_in[7];
    const float* b1  = (const float*)d_in[8];
    const float* ws2 = (const float*)d_in[9];
    const float* wn2 = (const float*)d_in[10];
    const float* b2  = (const float*)d_in[11];
    const float* gamma0 = (const float*)d_in[12];
    const float* beta0  = (const float*)d_in[13];
    const float* gamma1 = (const float*)d_in[14];
    const float* beta1  = (const float*)d_in[15];
    float* out = (float*)d_out;

    void *hAp, *whip, *wlop;
    cudaGetSymbolAddress(&hAp, g_hA);
    cudaGetSymbolAddress(&whip, g_Whi);
    cudaGetSymbolAddress(&wlop, g_Wlo);
    float* hA = (float*)hAp;
    const __nv_bfloat16* whi = (const __nv_bfloat16*)whip;
    const __nv_bfloat16* wlo = (const __nv_bfloat16*)wlop;

    const int SMEM128 = 2 * 16384 + 2 * 128 * 128;   // 65536
    const int SMEM64  = 2 * 16384 + 2 * 64 * 128;    // 49152
    cudaFuncSetAttribute(sage_mma<128, 0>, cudaFuncAttributeMaxDynamicSharedMemorySize, SMEM128);
    cudaFuncSetAttribute(sage_mma<64, 1>,  cudaFuncAttributeMaxDynamicSharedMemorySize, SMEM64);

    const int egrid = (NE + 255) / 256;              // 6250
    const int mgrid = (NN + 127) / 128;              // 782
    const int agrid = (NN * 32 + 255) / 256;         // 12500
    const int ngrid = (NN * 32 + 255) / 256;         // warp-per-node: 12500
    const int sgrid = (NN + 511) / 512;              // 196

    // ---- CSR build + prep ----
    convert_kernel<<<egrid, 256>>>(src, dst);                           // 1
    scan_local_kernel<<<NBLK, 256>>>();                                 // 2
    scan_addb_kernel<<<sgrid, 512>>>();                                 // 3
    prep_kernel<<<XBLK + 320, 256>>>(x, ws0, wn0, ws1, wn1, ws2, wn2);  // 4
    csr_fill_kernel<<<egrid, 256>>>();                                  // 5

    // ---- layer 0 ----
    aggregate_kernel<<<ngrid, 256>>>();                                 // 6
    sage_mma<128, 0><<<mgrid, 256, SMEM128>>>(b0, hA, whi, wlo);        // 7
    bn_apply_kernel<<<agrid, 256>>>(gamma0, beta0, hA);                 // 8

    // ---- layer 1 ----
    aggregate_kernel<<<ngrid, 256>>>();                                 // 9
    sage_mma<128, 0><<<mgrid, 256, SMEM128>>>(b1, hA, whi + 32768, wlo + 32768); // 10
    bn_apply_kernel<<<agrid, 256>>>(gamma1, beta1, hA);                 // 11

    // ---- layer 2 (+ fused log_softmax) ----
    aggregate_kernel<<<ngrid, 256>>>();                                 // 12
    sage_mma<64, 1><<<mgrid, 256, SMEM64>>>(b2, out, whi + 65536, wlo + 65536);  // 13
}

// round 12
// speedup vs baseline: 1.8013x; 1.0215x over previous
#include <cuda_runtime.h>
#include <cuda_bf16.h>
#include <cuda_fp16.h>
#include <math.h>
#include <stdint.h>

#define NN 100000
#define NE 1600000
#define HID 128
#define OUTF 64
#define NBLK ((NN + 255) / 256)   // 391 scan blocks
#define EGRID ((NE + 255) / 256)  // 6250 edge blocks
#define XBLK 12500                // NN*32/256 float4 chunks of x

// ---------------- scratch (static device globals; no allocations) ----------
__device__ int   g_src[NE];
__device__ int   g_dst[NE];
__device__ int   g_cnt[NN];
__device__ int   g_off[NN];
__device__ int   g_cur[NN];
__device__ int   g_csr[NE];
__device__ unsigned long long g_state[NBLK];   // decoupled-lookback scan state
__device__ int   g_ticket;
__device__ __align__(16) float g_hA[NN * HID];            // GEMM linear out
__device__ __align__(16) __half g_h16[NN * HID];          // fp16 gather source
__device__ __align__(16) __nv_bfloat16 g_Ahi[NN * 256];   // A = [h | agg] hi split
__device__ __align__(16) __nv_bfloat16 g_Alo[NN * 256];   // A lo split
__device__ __align__(16) __nv_bfloat16 g_Whi[320 * 256];  // W^T hi, layers at 0/32768/65536
__device__ __align__(16) __nv_bfloat16 g_Wlo[320 * 256];  // W^T lo
__device__ __align__(16) float g_bn[2][HID];              // [0]=sum [1]=sumsq

// ---------------- ptx helpers (all sm_80-era, no arch-'a' features) --------
__device__ __forceinline__ uint32_t smem_u32(const void* p) {
    uint32_t a;
    asm("{ .reg .u64 t; cvta.to.shared.u64 t, %1; cvt.u32.u64 %0, t; }"
        : "=r"(a) : "l"(p));
    return a;
}
__device__ __forceinline__ uint32_t sw128(uint32_t b) { return b ^ ((b >> 3) & 0x70); }

__device__ __forceinline__ void cp16(uint32_t sdst, const void* gsrc) {
    asm volatile("cp.async.cg.shared.global [%0], [%1], 16;"
                 :: "r"(sdst), "l"(gsrc) : "memory");
}
__device__ __forceinline__ void cp_commit() {
    asm volatile("cp.async.commit_group;" ::: "memory");
}
template<int W> __device__ __forceinline__ void cp_wait() {
    asm volatile("cp.async.wait_group %0;" :: "n"(W) : "memory");
}
__device__ __forceinline__ void ldm_x4(uint32_t* r, uint32_t a) {
    asm volatile("ldmatrix.sync.aligned.m8n8.x4.shared.b16 {%0,%1,%2,%3}, [%4];"
                 : "=r"(r[0]), "=r"(r[1]), "=r"(r[2]), "=r"(r[3]) : "r"(a));
}
__device__ __forceinline__ void ldm_x2(uint32_t* r, uint32_t a) {
    asm volatile("ldmatrix.sync.aligned.m8n8.x2.shared.b16 {%0,%1}, [%2];"
                 : "=r"(r[0]), "=r"(r[1]) : "r"(a));
}
__device__ __forceinline__ void mma_bf16(float* d, const uint32_t* a, const uint32_t* b) {
    asm volatile("mma.sync.aligned.m16n8k16.row.col.f32.bf16.bf16.f32 "
                 "{%0,%1,%2,%3}, {%4,%5,%6,%7}, {%8,%9}, {%0,%1,%2,%3};"
                 : "+f"(d[0]), "+f"(d[1]), "+f"(d[2]), "+f"(d[3])
                 : "r"(a[0]), "r"(a[1]), "r"(a[2]), "r"(a[3]),
                   "r"(b[0]), "r"(b[1]));
}
__device__ __forceinline__ uint32_t pack2(float a, float b) {
    __nv_bfloat162 t = __floats2bfloat162_rn(a, b);
    return *(uint32_t*)&t;
}
__device__ __forceinline__ void split_store(__nv_bfloat16* hi, __nv_bfloat16* lo,
                                            size_t off, float4 v) {
    float hx = __bfloat162float(__float2bfloat16_rn(v.x));
    float hy = __bfloat162float(__float2bfloat16_rn(v.y));
    float hz = __bfloat162float(__float2bfloat16_rn(v.z));
    float hw = __bfloat162float(__float2bfloat16_rn(v.w));
    uint2 H = make_uint2(pack2(v.x, v.y), pack2(v.z, v.w));
    uint2 L = make_uint2(pack2(v.x - hx, v.y - hy), pack2(v.z - hz, v.w - hw));
    *(uint2*)(hi + off) = H;
    *(uint2*)(lo + off) = L;
}
__device__ __forceinline__ uint2 pack_h16(float4 v) {
    __half2 a = __floats2half2_rn(v.x, v.y);
    __half2 b = __floats2half2_rn(v.z, v.w);
    return make_uint2(*(uint32_t*)&a, *(uint32_t*)&b);
}

// ---------------- kernel 1: convert edges + scan-state reset + prep --------
// Blocks [0,EGRID): edge convert + degree count (+block 0 resets scan state).
// Blocks [EGRID, EGRID+XBLK): x -> bf16 hi/lo split + fp16 copy.
// Blocks [EGRID+XBLK, +320): weight transpose + bf16 hi/lo split.
__global__ __launch_bounds__(256) void convert_prep_kernel(
    const void* srcv, const void* dstv, const float* __restrict__ x,
    const float* __restrict__ ws0, const float* __restrict__ wn0,
    const float* __restrict__ ws1, const float* __restrict__ wn1,
    const float* __restrict__ ws2, const float* __restrict__ wn2)
{
    int b = blockIdx.x;
    if (b < EGRID) {
        if (b == 0) {
            if (threadIdx.x == 0) g_ticket = 0;
            for (int j = threadIdx.x; j < NBLK; j += 256) g_state[j] = 0ull;
        }
        __shared__ int s_ok;
        const unsigned int* p = (const unsigned int*)srcv;
        if (threadIdx.x == 0) s_ok = 1;
        __syncthreads();
        if (threadIdx.x < 64) {
            // int64 with values < 2^31 -> all high words zero
            if (p[2 * threadIdx.x + 1] != 0u) s_ok = 0;
        }
        __syncthreads();
        int idx64 = s_ok;
        int e = b * 256 + threadIdx.x;
        if (e >= NE) return;
        int s, d;
        if (idx64) {
            s = (int)((const long long*)srcv)[e];
            d = (int)((const long long*)dstv)[e];
        } else {
            s = ((const int*)srcv)[e];
            d = ((const int*)dstv)[e];
        }
        g_src[e] = s;
        g_dst[e] = d;
        atomicAdd(&g_cnt[d], 1);
    } else if (b < EGRID + XBLK) {
        int idx = (b - EGRID) * 256 + threadIdx.x;   // float4 units over NN*128
        float4 v = ((const float4*)x)[idx];
        int row = idx >> 5;
        int c = (idx & 31) * 4;
        split_store(g_Ahi, g_Alo, (size_t)row * 256 + c, v);
        *(uint2*)(g_h16 + (size_t)row * HID + c) = pack_h16(v);
    } else {
        int i = (b - EGRID - XBLK) * 256 + threadIdx.x;  // 0..81919
        const float *ws, *wn;
        int base, cols;
        if (i < 32768)      { ws = ws0; wn = wn0; base = 0;     cols = HID;  }
        else if (i < 65536) { ws = ws1; wn = wn1; base = 32768; cols = HID;  i -= 32768; }
        else                { ws = ws2; wn = wn2; base = 65536; cols = OUTF; i -= 65536; }
        int n = i >> 8;
        int k = i & 255;
        float v = (k < 128) ? ws[k * cols + n] : wn[(k - 128) * cols + n];
        __nv_bfloat16 h = __float2bfloat16_rn(v);
        g_Whi[base + n * 256 + k] = h;
        g_Wlo[base + n * 256 + k] = __float2bfloat16_rn(v - __bfloat162float(h));
    }
}

// ---------------- kernel 2: single-pass scan (decoupled lookback) ----------
// state word: status<<32 | value. status 0=invalid, 1=block aggregate,
// 2=inclusive prefix. Ticket order guarantees predecessors are scheduled.
__global__ __launch_bounds__(256) void scan_kernel() {
    __shared__ int s[256];
    __shared__ int sbid, sprefix;
    if (threadIdx.x == 0) sbid = atomicAdd(&g_ticket, 1);
    __syncthreads();
    int bid = sbid;
    int i = bid * 256 + threadIdx.x;
    int v = (i < NN) ? g_cnt[i] : 0;
    if (i < NN) g_cnt[i] = 0;          // reset for next replay
    s[threadIdx.x] = v;
    __syncthreads();
#pragma unroll
    for (int off = 1; off < 256; off <<= 1) {
        int t = (threadIdx.x >= off) ? s[threadIdx.x - off] : 0;
        __syncthreads();
        s[threadIdx.x] += t;
        __syncthreads();
    }
    int total = s[255];
    if (threadIdx.x == 0) {
        if (bid == 0) {
            atomicExch(&g_state[0], (2ull << 32) | (unsigned)total);
            sprefix = 0;
        } else {
            atomicExch(&g_state[bid], (1ull << 32) | (unsigned)total);
            int prefix = 0;
            int j = bid - 1;
            while (true) {
                unsigned long long st = *(volatile unsigned long long*)&g_state[j];
                unsigned stat = (unsigned)(st >> 32);
                if (stat == 0u) continue;
                prefix += (int)(st & 0xffffffffu);
                if (stat == 2u) break;
                j--;
            }
            atomicExch(&g_state[bid], (2ull << 32) | (unsigned)(prefix + total));
            sprefix = prefix;
        }
    }
    __syncthreads();
    if (i < NN) {
        int o = sprefix + s[threadIdx.x] - v;   // global exclusive prefix
        g_off[i] = o;
        g_cur[i] = o;
    }
}

// ---------------- kernel 3: CSR fill ---------------------------------------
__global__ void csr_fill_kernel() {
    int e = blockIdx.x * blockDim.x + threadIdx.x;
    if (e >= NE) return;
    int pos = atomicAdd(&g_cur[g_dst[e]], 1);
    g_csr[pos] = g_src[e];
}

// ---------------- kernel 4: aggregation (profiled slot) --------------------
// CSR gather of fp16 rows, warp-per-node, 4 rows in flight (MLP), fp32 acc,
// mean via 1/deg, bf16 hi/lo split out. Block 0 zeroes BN accumulators.
__global__ __launch_bounds__(256) void aggregate_kernel() {
    if (blockIdx.x == 0 && threadIdx.x < 256)
        ((float*)g_bn)[threadIdx.x] = 0.0f;
    int node = (blockIdx.x * blockDim.x + threadIdx.x) >> 5;
    int lane = threadIdx.x & 31;
    if (node >= NN) return;
    int beg = g_off[node];
    int end = (node == NN - 1) ? NE : g_off[node + 1];
    float4 acc = make_float4(0.f, 0.f, 0.f, 0.f);
    int i = beg;
    for (; i + 4 <= end; i += 4) {
        int s0 = g_csr[i];
        int s1 = g_csr[i + 1];
        int s2 = g_csr[i + 2];
        int s3 = g_csr[i + 3];
        uint2 u0 = ((const uint2*)(g_h16 + (size_t)s0 * HID))[lane];
        uint2 u1 = ((const uint2*)(g_h16 + (size_t)s1 * HID))[lane];
        uint2 u2 = ((const uint2*)(g_h16 + (size_t)s2 * HID))[lane];
        uint2 u3 = ((const uint2*)(g_h16 + (size_t)s3 * HID))[lane];
        float2 a0 = __half22float2(*(__half2*)&u0.x);
        float2 b0 = __half22float2(*(__half2*)&u0.y);
        float2 a1 = __half22float2(*(__half2*)&u1.x);
        float2 b1 = __half22float2(*(__half2*)&u1.y);
        float2 a2 = __half22float2(*(__half2*)&u2.x);
        float2 b2 = __half22float2(*(__half2*)&u2.y);
        float2 a3 = __half22float2(*(__half2*)&u3.x);
        float2 b3 = __half22float2(*(__half2*)&u3.y);
        acc.x += (a0.x + a1.x) + (a2.x + a3.x);
        acc.y += (a0.y + a1.y) + (a2.y + a3.y);
        acc.z += (b0.x + b1.x) + (b2.x + b3.x);
        acc.w += (b0.y + b1.y) + (b2.y + b3.y);
    }
    for (; i < end; i++) {
        int s = g_csr[i];
        uint2 u = ((const uint2*)(g_h16 + (size_t)s * HID))[lane];
        float2 a = __half22float2(*(__half2*)&u.x);
        float2 b = __half22float2(*(__half2*)&u.y);
        acc.x += a.x; acc.y += a.y; acc.z += b.x; acc.w += b.y;
    }
    float r = 1.0f / (float)max(end - beg, 1);
    acc.x *= r; acc.y *= r; acc.z *= r; acc.w *= r;
    split_store(g_Ahi, g_Alo, (size_t)node * 256 + 128 + lane * 4, acc);
}

// ---------------- mma.sync GEMM: D = A(128x256) @ W^T, bf16x2 split ---------
// Block 256 thr (8 warps), tile 128xCOLS, KC=32 double-buffered cp.async.
// Warp grid: COLS=128 -> 4Mx2N; COLS=64 -> 8Mx1N (log_softmax intra-warp).
// MODE 0: out = D + bias, BN sum/sumsq accumulated into g_bn (smem reduce).
// MODE 1: out = log_softmax(D + bias) rowwise.
template<int COLS, int MODE>
__global__ __launch_bounds__(256) void sage_mma(
    const float* __restrict__ bias, float* __restrict__ outp,
    const __nv_bfloat16* __restrict__ whi, const __nv_bfloat16* __restrict__ wlo)
{
    extern __shared__ __align__(1024) char smem[];
    constexpr int BB  = COLS * 128;          // B stage bytes
    constexpr int A1o = 16384;
    constexpr int B0o = 32768;
    constexpr int B1o = 32768 + BB;
    constexpr int NWN = (COLS == 128) ? 2 : 1;   // warps along N
    constexpr int NWM = 8 / NWN;                 // warps along M
    constexpr int MI  = 128 / (NWM * 16);        // m16 steps per warp (2 or 1)
    constexpr int WARP_N = COLS / NWN;           // 64
    constexpr int NI  = WARP_N / 8;              // 8

    const int tid  = threadIdx.x;
    const int wid  = tid >> 5;
    const int lane = tid & 31;
    const int wm   = wid / NWN;
    const int wn   = wid % NWN;
    const int row0 = blockIdx.x * 128;
    const uint32_t sb = smem_u32(smem);

    const int arow = wm * (MI * 16) + (lane & 15);   // + mi*16
    const int acb  = (lane >> 4) * 16;
    const int brow = wn * WARP_N + (lane & 7);       // + ni*8
    const int bcb  = ((lane >> 3) & 1) * 16;

    float acc[MI][NI][4];
#pragma unroll
    for (int mi = 0; mi < MI; mi++)
#pragma unroll
        for (int ni = 0; ni < NI; ni++)
#pragma unroll
            for (int q = 0; q < 4; q++) acc[mi][ni][q] = 0.0f;

    auto load_stage = [&](int ks, int buf) {
        uint32_t Ab = sb + (buf ? A1o : 0);
        uint32_t Bb = sb + (buf ? B1o : B0o);
#pragma unroll
        for (int i = 0; i < 4; i++) {                // A: 1024 16B chunks
            int u = tid + i * 256;
            int r = u >> 3, c = u & 7;
            int rowg = min(row0 + r, NN - 1);
            const __nv_bfloat16* g = (c < 4 ? g_Ahi : g_Alo)
                                   + (size_t)rowg * 256 + ks * 32 + (c & 3) * 8;
            cp16(Ab + sw128(r * 128 + c * 16), g);
        }
#pragma unroll
        for (int i = 0; i < COLS / 32; i++) {        // B: COLS*8 chunks
            int u = tid + i * 256;
            int n = u >> 3, c = u & 7;
            const __nv_bfloat16* g = (c < 4 ? whi : wlo)
                                   + (size_t)n * 256 + ks * 32 + (c & 3) * 8;
            cp16(Bb + sw128(n * 128 + c * 16), g);
        }
    };

    auto compute_stage = [&](int buf) {
        uint32_t Ab = sb + (buf ? A1o : 0);
        uint32_t Bb = sb + (buf ? B1o : B0o);
#pragma unroll
        for (int kk = 0; kk < 2; kk++) {             // two k16 steps per stage
            uint32_t bh[NI][2], bl[NI][2];
#pragma unroll
            for (int ni = 0; ni < NI; ni++) {
                uint32_t off = (uint32_t)(brow + ni * 8) * 128 + kk * 32 + bcb;
                ldm_x2(bh[ni], Bb + sw128(off));
                ldm_x2(bl[ni], Bb + sw128(off + 64));
            }
#pragma unroll
            for (int mi = 0; mi < MI; mi++) {
                uint32_t ah[4], al[4];
                uint32_t off = (uint32_t)(arow + mi * 16) * 128 + kk * 32 + acb;
                ldm_x4(ah, Ab + sw128(off));
                ldm_x4(al, Ab + sw128(off + 64));
#pragma unroll
                for (int ni = 0; ni < NI; ni++) {
                    mma_bf16(acc[mi][ni], ah, bh[ni]);   // hi*hi
                    mma_bf16(acc[mi][ni], ah, bl[ni]);   // hi*lo
                    mma_bf16(acc[mi][ni], al, bh[ni]);   // lo*hi
                }
            }
        }
    };

    load_stage(0, 0);
    cp_commit();
    for (int ks = 0; ks < 8; ks++) {
        if (ks < 7) {
            load_stage(ks + 1, (ks + 1) & 1);
            cp_commit();
            cp_wait<1>();
        } else {
            cp_wait<0>();
        }
        __syncthreads();
        compute_stage(ks & 1);
        __syncthreads();
    }

    // ---- epilogue: add bias into acc ----
#pragma unroll
    for (int mi = 0; mi < MI; mi++)
#pragma unroll
        for (int ni = 0; ni < NI; ni++) {
            int c = wn * WARP_N + ni * 8 + (lane & 3) * 2;
            float b0 = __ldg(bias + c), b1 = __ldg(bias + c + 1);
            acc[mi][ni][0] += b0; acc[mi][ni][1] += b1;
            acc[mi][ni][2] += b0; acc[mi][ni][3] += b1;
        }

    const int r_base = row0 + wm * (MI * 16) + (lane >> 2);

    if (MODE == 0) {
        // store + per-thread BN partials (row-guarded)
        float vs[2 * NI], vq[2 * NI];
#pragma unroll
        for (int j = 0; j < 2 * NI; j++) { vs[j] = 0.f; vq[j] = 0.f; }
#pragma unroll
        for (int mi = 0; mi < MI; mi++) {
            int rA = r_base + mi * 16;
            int rB = rA + 8;
            bool gA = rA < NN, gB = rB < NN;
#pragma unroll
            for (int ni = 0; ni < NI; ni++) {
                int c = wn * WARP_N + ni * 8 + (lane & 3) * 2;
                if (gA) {
                    float2 o = make_float2(acc[mi][ni][0], acc[mi][ni][1]);
                    *(float2*)(outp + (size_t)rA * COLS + c) = o;
                    vs[2 * ni] += o.x;     vq[2 * ni] += o.x * o.x;
                    vs[2 * ni + 1] += o.y; vq[2 * ni + 1] += o.y * o.y;
                }
                if (gB) {
                    float2 o = make_float2(acc[mi][ni][2], acc[mi][ni][3]);
                    *(float2*)(outp + (size_t)rB * COLS + c) = o;
                    vs[2 * ni] += o.x;     vq[2 * ni] += o.x * o.x;
                    vs[2 * ni + 1] += o.y; vq[2 * ni + 1] += o.y * o.y;
                }
            }
        }
        // block reduce in smem (stage buffers are dead now), then global atomics
        float* sred = (float*)smem;      // [0..127]=sum, [128..255]=sumsq
        sred[tid] = 0.0f;
        __syncthreads();
#pragma unroll
        for (int ni = 0; ni < NI; ni++) {
            int c = wn * WARP_N + ni * 8 + (lane & 3) * 2;
            atomicAdd(&sred[c],           vs[2 * ni]);
            atomicAdd(&sred[c + 1],       vs[2 * ni + 1]);
            atomicAdd(&sred[128 + c],     vq[2 * ni]);
            atomicAdd(&sred[128 + c + 1], vq[2 * ni + 1]);
        }
        __syncthreads();
        if (tid < 256) atomicAdd(&((float*)g_bn)[tid], sred[tid]);
    } else {
        // log_softmax over COLS=64: one warp owns all 64 cols of its rows.
#pragma unroll
        for (int mi = 0; mi < MI; mi++) {
            float mA = -INFINITY, mB = -INFINITY;
#pragma unroll
            for (int ni = 0; ni < NI; ni++) {
                mA = fmaxf(mA, fmaxf(acc[mi][ni][0], acc[mi][ni][1]));
                mB = fmaxf(mB, fmaxf(acc[mi][ni][2], acc[mi][ni][3]));
            }
#pragma unroll
            for (int off = 1; off <= 2; off <<= 1) {
                mA = fmaxf(mA, __shfl_xor_sync(0xffffffffu, mA, off));
                mB = fmaxf(mB, __shfl_xor_sync(0xffffffffu, mB, off));
            }
            float sA = 0.f, sB = 0.f;
#pragma unroll
            for (int ni = 0; ni < NI; ni++) {
                sA += expf(acc[mi][ni][0] - mA) + expf(acc[mi][ni][1] - mA);
                sB += expf(acc[mi][ni][2] - mB) + expf(acc[mi][ni][3] - mB);
            }
#pragma unroll
            for (int off = 1; off <= 2; off <<= 1) {
                sA += __shfl_xor_sync(0xffffffffu, sA, off);
                sB += __shfl_xor_sync(0xffffffffu, sB, off);
            }
            float lseA = mA + logf(sA);
            float lseB = mB + logf(sB);
            int rA = r_base + mi * 16;
            int rB = rA + 8;
#pragma unroll
            for (int ni = 0; ni < NI; ni++) {
                int c = wn * WARP_N + ni * 8 + (lane & 3) * 2;
                if (rA < NN) {
                    float2 o = make_float2(acc[mi][ni][0] - lseA, acc[mi][ni][1] - lseA);
                    *(float2*)(outp + (size_t)rA * COLS + c) = o;
                }
                if (rB < NN) {
                    float2 o = make_float2(acc[mi][ni][2] - lseB, acc[mi][ni][3] - lseB);
                    *(float2*)(outp + (size_t)rB * COLS + c) = o;
                }
            }
        }
    }
}

// ---------------- BN finalize (inline) + apply + ReLU + fp16 + split -------
__global__ __launch_bounds__(256) void bn_apply_kernel(
    const float* __restrict__ gamma, const float* __restrict__ beta,
    const float* __restrict__ in)
{
    __shared__ float sc[HID], sh[HID];
    if (threadIdx.x < HID) {
        int c = threadIdx.x;
        float s  = g_bn[0][c];
        float sq = g_bn[1][c];
        float mu  = s / (float)NN;
        float var = sq / (float)NN - mu * mu;
        float scv = gamma[c] * rsqrtf(var + 1e-5f);
        sc[c] = scv;
        sh[c] = beta[c] - mu * scv;
    }
    __syncthreads();
    int idx = blockIdx.x * blockDim.x + threadIdx.x;   // float4 units
    if (idx >= NN * 32) return;
    float4 v = ((const float4*)in)[idx];
    int row = idx >> 5;
    int c = (idx & 31) * 4;
    float4 o;
    o.x = fmaxf(fmaf(v.x, sc[c + 0], sh[c + 0]), 0.0f);
    o.y = fmaxf(fmaf(v.y, sc[c + 1], sh[c + 1]), 0.0f);
    o.z = fmaxf(fmaf(v.z, sc[c + 2], sh[c + 2]), 0.0f);
    o.w = fmaxf(fmaf(v.w, sc[c + 3], sh[c + 3]), 0.0f);
    *(uint2*)(g_h16 + (size_t)row * HID + c) = pack_h16(o);
    split_store(g_Ahi, g_Alo, (size_t)row * 256 + c, o);
}

// ---------------- launch ----------------------------------------------------
extern "C" void kernel_launch(void* const* d_in, const int* in_sizes, int n_in,
                              void* d_out, int out_size) {
    const float* x   = (const float*)d_in[0];
    const void*  src = d_in[1];
    const void*  dst = d_in[2];
    const float* ws0 = (const float*)d_in[3];
    const float* wn0 = (const float*)d_in[4];
    const float* b0  = (const float*)d_in[5];
    const float* ws1 = (const float*)d_in[6];
    const float* wn1 = (const float*)d_in[7];
    const float* b1  = (const float*)d_in[8];
    const float* ws2 = (const float*)d_in[9];
    const float* wn2 = (const float*)d_in[10];
    const float* b2  = (const float*)d_in[11];
    const float* gamma0 = (const float*)d_in[12];
    const float* beta0  = (const float*)d_in[13];
    const float* gamma1 = (const float*)d_in[14];
    const float* beta1  = (const float*)d_in[15];
    float* out = (float*)d_out;

    void *hAp, *whip, *wlop;
    cudaGetSymbolAddress(&hAp, g_hA);
    cudaGetSymbolAddress(&whip, g_Whi);
    cudaGetSymbolAddress(&wlop, g_Wlo);
    float* hA = (float*)hAp;
    const __nv_bfloat16* whi = (const __nv_bfloat16*)whip;
    const __nv_bfloat16* wlo = (const __nv_bfloat16*)wlop;

    const int SMEM128 = 2 * 16384 + 2 * 128 * 128;   // 65536
    const int SMEM64  = 2 * 16384 + 2 * 64 * 128;    // 49152
    cudaFuncSetAttribute(sage_mma<128, 0>, cudaFuncAttributeMaxDynamicSharedMemorySize, SMEM128);
    cudaFuncSetAttribute(sage_mma<64, 1>,  cudaFuncAttributeMaxDynamicSharedMemorySize, SMEM64);

    const int mgrid = (NN + 127) / 128;              // 782
    const int agrid = (NN * 32 + 255) / 256;         // 12500
    const int ngrid = (NN * 32 + 255) / 256;         // warp-per-node: 12500

    // 1: convert + scan-state reset + x/weight prep (disjoint block ranges)
    convert_prep_kernel<<<EGRID + XBLK + 320, 256>>>(
        src, dst, x, ws0, wn0, ws1, wn1, ws2, wn2);
    // 2: single-pass exclusive scan (decoupled lookback)
    scan_kernel<<<NBLK, 256>>>();
    // 3: CSR fill
    csr_fill_kernel<<<EGRID, 256>>>();

    // ---- layer 0 ----
    aggregate_kernel<<<ngrid, 256>>>();                                 // 4 <- profiled
    sage_mma<128, 0><<<mgrid, 256, SMEM128>>>(b0, hA, whi, wlo);        // 5
    bn_apply_kernel<<<agrid, 256>>>(gamma0, beta0, hA);                 // 6

    // ---- layer 1 ----
    aggregate_kernel<<<ngrid, 256>>>();                                 // 7
    sage_mma<128, 0><<<mgrid, 256, SMEM128>>>(b1, hA, whi + 32768, wlo + 32768); // 8
    bn_apply_kernel<<<agrid, 256>>>(gamma1, beta1, hA);                 // 9

    // ---- layer 2 (+ fused log_softmax) ----
    aggregate_kernel<<<ngrid, 256>>>();                                 // 10
    sage_mma<64, 1><<<mgrid, 256, SMEM64>>>(b2, out, whi + 65536, wlo + 65536);  // 11
}

// round 14
// speedup vs baseline: 2.1867x; 1.2139x over previous
#include <cuda_runtime.h>
#include <cuda_fp16.h>
#include <math.h>
#include <stdint.h>

#define NN 100000
#define NE 1600000
#define HID 128
#define OUTF 64
#define NBLK ((NN + 255) / 256)   // 391 scan blocks
#define EGRID ((NE + 255) / 256)  // 6250 edge blocks
#define XBLK 12500                // NN*32/256 float4 chunks of x

// ---------------- scratch (static device globals; no allocations) ----------
__device__ int   g_src[NE];
__device__ int   g_dst[NE];
__device__ int   g_cnt[NN];
__device__ int   g_off[NN];
__device__ int   g_cur[NN];
__device__ int   g_csr[NE];
__device__ unsigned long long g_state[NBLK];   // decoupled-lookback scan state
__device__ int   g_ticket;
__device__ __align__(16) float g_hA[NN * HID];        // GEMM linear out (fp32)
__device__ __align__(16) __half g_A16[NN * 256];      // A = [h | agg] fp16
__device__ __align__(16) __half g_W16[320 * 256];     // W^T fp16, layers at 0/32768/65536
__device__ __align__(16) float g_bn[2][HID];          // [0]=sum [1]=sumsq

// ---------------- ptx helpers (all sm_80-era, no arch-'a' features) --------
__device__ __forceinline__ uint32_t smem_u32(const void* p) {
    uint32_t a;
    asm("{ .reg .u64 t; cvta.to.shared.u64 t, %1; cvt.u32.u64 %0, t; }"
        : "=r"(a) : "l"(p));
    return a;
}
__device__ __forceinline__ uint32_t sw128(uint32_t b) { return b ^ ((b >> 3) & 0x70); }

__device__ __forceinline__ void cp16(uint32_t sdst, const void* gsrc) {
    asm volatile("cp.async.cg.shared.global [%0], [%1], 16;"
                 :: "r"(sdst), "l"(gsrc) : "memory");
}
__device__ __forceinline__ void cp_commit() {
    asm volatile("cp.async.commit_group;" ::: "memory");
}
template<int W> __device__ __forceinline__ void cp_wait() {
    asm volatile("cp.async.wait_group %0;" :: "n"(W) : "memory");
}
__device__ __forceinline__ void ldm_x4(uint32_t* r, uint32_t a) {
    asm volatile("ldmatrix.sync.aligned.m8n8.x4.shared.b16 {%0,%1,%2,%3}, [%4];"
                 : "=r"(r[0]), "=r"(r[1]), "=r"(r[2]), "=r"(r[3]) : "r"(a));
}
__device__ __forceinline__ void ldm_x2(uint32_t* r, uint32_t a) {
    asm volatile("ldmatrix.sync.aligned.m8n8.x2.shared.b16 {%0,%1}, [%2];"
                 : "=r"(r[0]), "=r"(r[1]) : "r"(a));
}
__device__ __forceinline__ void mma_f16(float* d, const uint32_t* a, const uint32_t* b) {
    asm volatile("mma.sync.aligned.m16n8k16.row.col.f32.f16.f16.f32 "
                 "{%0,%1,%2,%3}, {%4,%5,%6,%7}, {%8,%9}, {%0,%1,%2,%3};"
                 : "+f"(d[0]), "+f"(d[1]), "+f"(d[2]), "+f"(d[3])
                 : "r"(a[0]), "r"(a[1]), "r"(a[2]), "r"(a[3]),
                   "r"(b[0]), "r"(b[1]));
}
__device__ __forceinline__ uint2 pack_h16(float4 v) {
    __half2 a = __floats2half2_rn(v.x, v.y);
    __half2 b = __floats2half2_rn(v.z, v.w);
    return make_uint2(*(uint32_t*)&a, *(uint32_t*)&b);
}

// ---------------- kernel 1: convert edges + scan-state reset + prep --------
// Blocks [0,EGRID): edge convert + degree count (+block 0 resets scan state).
// Blocks [EGRID, EGRID+XBLK): x -> fp16 into A cols 0..127.
// Blocks [EGRID+XBLK, +320): weight transpose -> fp16.
__global__ __launch_bounds__(256) void convert_prep_kernel(
    const void* srcv, const void* dstv, const float* __restrict__ x,
    const float* __restrict__ ws0, const float* __restrict__ wn0,
    const float* __restrict__ ws1, const float* __restrict__ wn1,
    const float* __restrict__ ws2, const float* __restrict__ wn2)
{
    int b = blockIdx.x;
    if (b < EGRID) {
        if (b == 0) {
            if (threadIdx.x == 0) g_ticket = 0;
            for (int j = threadIdx.x; j < NBLK; j += 256) g_state[j] = 0ull;
        }
        __shared__ int s_ok;
        const unsigned int* p = (const unsigned int*)srcv;
        if (threadIdx.x == 0) s_ok = 1;
        __syncthreads();
        if (threadIdx.x < 64) {
            // int64 with values < 2^31 -> all high words zero
            if (p[2 * threadIdx.x + 1] != 0u) s_ok = 0;
        }
        __syncthreads();
        int idx64 = s_ok;
        int e = b * 256 + threadIdx.x;
        if (e >= NE) return;
        int s, d;
        if (idx64) {
            s = (int)((const long long*)srcv)[e];
            d = (int)((const long long*)dstv)[e];
        } else {
            s = ((const int*)srcv)[e];
            d = ((const int*)dstv)[e];
        }
        g_src[e] = s;
        g_dst[e] = d;
        atomicAdd(&g_cnt[d], 1);
    } else if (b < EGRID + XBLK) {
        int idx = (b - EGRID) * 256 + threadIdx.x;   // float4 units over NN*128
        float4 v = ((const float4*)x)[idx];
        int row = idx >> 5;
        int c = (idx & 31) * 4;
        *(uint2*)(g_A16 + (size_t)row * 256 + c) = pack_h16(v);
    } else {
        int i = (b - EGRID - XBLK) * 256 + threadIdx.x;  // 0..81919
        const float *ws, *wn;
        int base, cols;
        if (i < 32768)      { ws = ws0; wn = wn0; base = 0;     cols = HID;  }
        else if (i < 65536) { ws = ws1; wn = wn1; base = 32768; cols = HID;  i -= 32768; }
        else                { ws = ws2; wn = wn2; base = 65536; cols = OUTF; i -= 65536; }
        int n = i >> 8;
        int k = i & 255;
        float v = (k < 128) ? ws[k * cols + n] : wn[(k - 128) * cols + n];
        g_W16[base + n * 256 + k] = __float2half_rn(v);
    }
}

// ---------------- kernel 2: single-pass scan (decoupled lookback) ----------
__global__ __launch_bounds__(256) void scan_kernel() {
    __shared__ int s[256];
    __shared__ int sbid, sprefix;
    if (threadIdx.x == 0) sbid = atomicAdd(&g_ticket, 1);
    __syncthreads();
    int bid = sbid;
    int i = bid * 256 + threadIdx.x;
    int v = (i < NN) ? g_cnt[i] : 0;
    if (i < NN) g_cnt[i] = 0;          // reset for next replay
    s[threadIdx.x] = v;
    __syncthreads();
#pragma unroll
    for (int off = 1; off < 256; off <<= 1) {
        int t = (threadIdx.x >= off) ? s[threadIdx.x - off] : 0;
        __syncthreads();
        s[threadIdx.x] += t;
        __syncthreads();
    }
    int total = s[255];
    if (threadIdx.x == 0) {
        if (bid == 0) {
            atomicExch(&g_state[0], (2ull << 32) | (unsigned)total);
            sprefix = 0;
        } else {
            atomicExch(&g_state[bid], (1ull << 32) | (unsigned)total);
            int prefix = 0;
            int j = bid - 1;
            while (true) {
                unsigned long long st = *(volatile unsigned long long*)&g_state[j];
                unsigned stat = (unsigned)(st >> 32);
                if (stat == 0u) continue;
                prefix += (int)(st & 0xffffffffu);
                if (stat == 2u) break;
                j--;
            }
            atomicExch(&g_state[bid], (2ull << 32) | (unsigned)(prefix + total));
            sprefix = prefix;
        }
    }
    __syncthreads();
    if (i < NN) {
        int o = sprefix + s[threadIdx.x] - v;   // global exclusive prefix
        g_off[i] = o;
        g_cur[i] = o;
    }
}

// ---------------- kernel 3: CSR fill ---------------------------------------
__global__ void csr_fill_kernel() {
    int e = blockIdx.x * blockDim.x + threadIdx.x;
    if (e >= NE) return;
    int pos = atomicAdd(&g_cur[g_dst[e]], 1);
    g_csr[pos] = g_src[e];
}

// ---------------- kernel 4: aggregation (profiled slot) --------------------
// CSR gather of fp16 rows (A cols 0..127), warp-per-node, 4 rows in flight,
// fp32 accumulate, mean, fp16 out to A cols 128..255. Block 0 zeroes BN.
__global__ __launch_bounds__(256) void aggregate_kernel() {
    if (blockIdx.x == 0 && threadIdx.x < 256)
        ((float*)g_bn)[threadIdx.x] = 0.0f;
    int node = (blockIdx.x * blockDim.x + threadIdx.x) >> 5;
    int lane = threadIdx.x & 31;
    if (node >= NN) return;
    int beg = g_off[node];
    int end = (node == NN - 1) ? NE : g_off[node + 1];
    float4 acc = make_float4(0.f, 0.f, 0.f, 0.f);
    int i = beg;
    for (; i + 4 <= end; i += 4) {
        int s0 = g_csr[i];
        int s1 = g_csr[i + 1];
        int s2 = g_csr[i + 2];
        int s3 = g_csr[i + 3];
        uint2 u0 = ((const uint2*)(g_A16 + (size_t)s0 * 256))[lane];
        uint2 u1 = ((const uint2*)(g_A16 + (size_t)s1 * 256))[lane];
        uint2 u2 = ((const uint2*)(g_A16 + (size_t)s2 * 256))[lane];
        uint2 u3 = ((const uint2*)(g_A16 + (size_t)s3 * 256))[lane];
        float2 a0 = __half22float2(*(__half2*)&u0.x);
        float2 b0 = __half22float2(*(__half2*)&u0.y);
        float2 a1 = __half22float2(*(__half2*)&u1.x);
        float2 b1 = __half22float2(*(__half2*)&u1.y);
        float2 a2 = __half22float2(*(__half2*)&u2.x);
        float2 b2 = __half22float2(*(__half2*)&u2.y);
        float2 a3 = __half22float2(*(__half2*)&u3.x);
        float2 b3 = __half22float2(*(__half2*)&u3.y);
        acc.x += (a0.x + a1.x) + (a2.x + a3.x);
        acc.y += (a0.y + a1.y) + (a2.y + a3.y);
        acc.z += (b0.x + b1.x) + (b2.x + b3.x);
        acc.w += (b0.y + b1.y) + (b2.y + b3.y);
    }
    for (; i < end; i++) {
        int s = g_csr[i];
        uint2 u = ((const uint2*)(g_A16 + (size_t)s * 256))[lane];
        float2 a = __half22float2(*(__half2*)&u.x);
        float2 b = __half22float2(*(__half2*)&u.y);
        acc.x += a.x; acc.y += a.y; acc.z += b.x; acc.w += b.y;
    }
    float r = 1.0f / (float)max(end - beg, 1);
    acc.x *= r; acc.y *= r; acc.z *= r; acc.w *= r;
    *(uint2*)(g_A16 + (size_t)node * 256 + 128 + lane * 4) = pack_h16(acc);
}

// ---------------- mma.sync GEMM: D = A(128x256) @ W^T, fp16 single-term ----
// Block 256 thr (8 warps), tile 128xCOLS, KC=64 (=128B row, SW128 atom),
// 4 stages double-buffered cp.async.
// Warp grid: COLS=128 -> 4Mx2N; COLS=64 -> 8Mx1N (log_softmax intra-warp).
// MODE 0: out = D + bias, BN sum/sumsq accumulated into g_bn (smem reduce).
// MODE 1: out = log_softmax(D + bias) rowwise.
template<int COLS, int MODE>
__global__ __launch_bounds__(256) void sage_mma(
    const float* __restrict__ bias, float* __restrict__ outp,
    const __half* __restrict__ w16)
{
    extern __shared__ __align__(1024) char smem[];
    constexpr int BB  = COLS * 128;          // B stage bytes
    constexpr int A1o = 16384;
    constexpr int B0o = 32768;
    constexpr int B1o = 32768 + BB;
    constexpr int NWN = (COLS == 128) ? 2 : 1;   // warps along N
    constexpr int NWM = 8 / NWN;                 // warps along M
    constexpr int MI  = 128 / (NWM * 16);        // m16 steps per warp (2 or 1)
    constexpr int WARP_N = COLS / NWN;           // 64
    constexpr int NI  = WARP_N / 8;              // 8

    const int tid  = threadIdx.x;
    const int wid  = tid >> 5;
    const int lane = tid & 31;
    const int wm   = wid / NWN;
    const int wn   = wid % NWN;
    const int row0 = blockIdx.x * 128;
    const uint32_t sb = smem_u32(smem);

    const int arow = wm * (MI * 16) + (lane & 15);   // + mi*16
    const int acb  = (lane >> 4) * 16;
    const int brow = wn * WARP_N + (lane & 7);       // + ni*8
    const int bcb  = ((lane >> 3) & 1) * 16;

    float acc[MI][NI][4];
#pragma unroll
    for (int mi = 0; mi < MI; mi++)
#pragma unroll
        for (int ni = 0; ni < NI; ni++)
#pragma unroll
            for (int q = 0; q < 4; q++) acc[mi][ni][q] = 0.0f;

    auto load_stage = [&](int ks, int buf) {
        uint32_t Ab = sb + (buf ? A1o : 0);
        uint32_t Bb = sb + (buf ? B1o : B0o);
#pragma unroll
        for (int i = 0; i < 4; i++) {                // A: 128 rows x 8 chunks
            int u = tid + i * 256;
            int r = u >> 3, c = u & 7;
            int rowg = min(row0 + r, NN - 1);
            cp16(Ab + sw128(r * 128 + c * 16),
                 g_A16 + (size_t)rowg * 256 + ks * 64 + c * 8);
        }
#pragma unroll
        for (int i = 0; i < COLS / 32; i++) {        // B: COLS x 8 chunks
            int u = tid + i * 256;
            int n = u >> 3, c = u & 7;
            cp16(Bb + sw128(n * 128 + c * 16),
                 w16 + (size_t)n * 256 + ks * 64 + c * 8);
        }
    };

    auto compute_stage = [&](int buf) {
        uint32_t Ab = sb + (buf ? A1o : 0);
        uint32_t Bb = sb + (buf ? B1o : B0o);
#pragma unroll
        for (int kk = 0; kk < 4; kk++) {             // four k16 steps per stage
            uint32_t bf[NI][2];
#pragma unroll
            for (int ni = 0; ni < NI; ni++) {
                uint32_t off = (uint32_t)(brow + ni * 8) * 128 + kk * 32 + bcb;
                ldm_x2(bf[ni], Bb + sw128(off));
            }
#pragma unroll
            for (int mi = 0; mi < MI; mi++) {
                uint32_t af[4];
                uint32_t off = (uint32_t)(arow + mi * 16) * 128 + kk * 32 + acb;
                ldm_x4(af, Ab + sw128(off));
#pragma unroll
                for (int ni = 0; ni < NI; ni++)
                    mma_f16(acc[mi][ni], af, bf[ni]);
            }
        }
    };

    load_stage(0, 0);
    cp_commit();
    for (int ks = 0; ks < 4; ks++) {
        if (ks < 3) {
            load_stage(ks + 1, (ks + 1) & 1);
            cp_commit();
            cp_wait<1>();
        } else {
            cp_wait<0>();
        }
        __syncthreads();
        compute_stage(ks & 1);
        __syncthreads();
    }

    // ---- epilogue: add bias into acc ----
#pragma unroll
    for (int mi = 0; mi < MI; mi++)
#pragma unroll
        for (int ni = 0; ni < NI; ni++) {
            int c = wn * WARP_N + ni * 8 + (lane & 3) * 2;
            float b0 = __ldg(bias + c), b1 = __ldg(bias + c + 1);
            acc[mi][ni][0] += b0; acc[mi][ni][1] += b1;
            acc[mi][ni][2] += b0; acc[mi][ni][3] += b1;
        }

    const int r_base = row0 + wm * (MI * 16) + (lane >> 2);

    if (MODE == 0) {
        // store + per-thread BN partials (row-guarded)
        float vs[2 * NI], vq[2 * NI];
#pragma unroll
        for (int j = 0; j < 2 * NI; j++) { vs[j] = 0.f; vq[j] = 0.f; }
#pragma unroll
        for (int mi = 0; mi < MI; mi++) {
            int rA = r_base + mi * 16;
            int rB = rA + 8;
            bool gA = rA < NN, gB = rB < NN;
#pragma unroll
            for (int ni = 0; ni < NI; ni++) {
                int c = wn * WARP_N + ni * 8 + (lane & 3) * 2;
                if (gA) {
                    float2 o = make_float2(acc[mi][ni][0], acc[mi][ni][1]);
                    *(float2*)(outp + (size_t)rA * COLS + c) = o;
                    vs[2 * ni] += o.x;     vq[2 * ni] += o.x * o.x;
                    vs[2 * ni + 1] += o.y; vq[2 * ni + 1] += o.y * o.y;
                }
                if (gB) {
                    float2 o = make_float2(acc[mi][ni][2], acc[mi][ni][3]);
                    *(float2*)(outp + (size_t)rB * COLS + c) = o;
                    vs[2 * ni] += o.x;     vq[2 * ni] += o.x * o.x;
                    vs[2 * ni + 1] += o.y; vq[2 * ni + 1] += o.y * o.y;
                }
            }
        }
        // block reduce in smem (stage buffers are dead now), then global atomics
        float* sred = (float*)smem;      // [0..127]=sum, [128..255]=sumsq
        sred[tid] = 0.0f;
        __syncthreads();
#pragma unroll
        for (int ni = 0; ni < NI; ni++) {
            int c = wn * WARP_N + ni * 8 + (lane & 3) * 2;
            atomicAdd(&sred[c],           vs[2 * ni]);
            atomicAdd(&sred[c + 1],       vs[2 * ni + 1]);
            atomicAdd(&sred[128 + c],     vq[2 * ni]);
            atomicAdd(&sred[128 + c + 1], vq[2 * ni + 1]);
        }
        __syncthreads();
        if (tid < 256) atomicAdd(&((float*)g_bn)[tid], sred[tid]);
    } else {
        // log_softmax over COLS=64: one warp owns all 64 cols of its rows.
#pragma unroll
        for (int mi = 0; mi < MI; mi++) {
            float mA = -INFINITY, mB = -INFINITY;
#pragma unroll
            for (int ni = 0; ni < NI; ni++) {
                mA = fmaxf(mA, fmaxf(acc[mi][ni][0], acc[mi][ni][1]));
                mB = fmaxf(mB, fmaxf(acc[mi][ni][2], acc[mi][ni][3]));
            }
#pragma unroll
            for (int off = 1; off <= 2; off <<= 1) {
                mA = fmaxf(mA, __shfl_xor_sync(0xffffffffu, mA, off));
                mB = fmaxf(mB, __shfl_xor_sync(0xffffffffu, mB, off));
            }
            float sA = 0.f, sB = 0.f;
#pragma unroll
            for (int ni = 0; ni < NI; ni++) {
                sA += expf(acc[mi][ni][0] - mA) + expf(acc[mi][ni][1] - mA);
                sB += expf(acc[mi][ni][2] - mB) + expf(acc[mi][ni][3] - mB);
            }
#pragma unroll
            for (int off = 1; off <= 2; off <<= 1) {
                sA += __shfl_xor_sync(0xffffffffu, sA, off);
                sB += __shfl_xor_sync(0xffffffffu, sB, off);
            }
            float lseA = mA + logf(sA);
            float lseB = mB + logf(sB);
            int rA = r_base + mi * 16;
            int rB = rA + 8;
#pragma unroll
            for (int ni = 0; ni < NI; ni++) {
                int c = wn * WARP_N + ni * 8 + (lane & 3) * 2;
                if (rA < NN) {
                    float2 o = make_float2(acc[mi][ni][0] - lseA, acc[mi][ni][1] - lseA);
                    *(float2*)(outp + (size_t)rA * COLS + c) = o;
                }
                if (rB < NN) {
                    float2 o = make_float2(acc[mi][ni][2] - lseB, acc[mi][ni][3] - lseB);
                    *(float2*)(outp + (size_t)rB * COLS + c) = o;
                }
            }
        }
    }
}

// ---------------- BN finalize (inline) + apply + ReLU -> fp16 A cols 0..127
__global__ __launch_bounds__(256) void bn_apply_kernel(
    const float* __restrict__ gamma, const float* __restrict__ beta,
    const float* __restrict__ in)
{
    __shared__ float sc[HID], sh[HID];
    if (threadIdx.x < HID) {
        int c = threadIdx.x;
        float s  = g_bn[0][c];
        float sq = g_bn[1][c];
        float mu  = s / (float)NN;
        float var = sq / (float)NN - mu * mu;
        float scv = gamma[c] * rsqrtf(var + 1e-5f);
        sc[c] = scv;
        sh[c] = beta[c] - mu * scv;
    }
    __syncthreads();
    int idx = blockIdx.x * blockDim.x + threadIdx.x;   // float4 units
    if (idx >= NN * 32) return;
    float4 v = ((const float4*)in)[idx];
    int row = idx >> 5;
    int c = (idx & 31) * 4;
    float4 o;
    o.x = fmaxf(fmaf(v.x, sc[c + 0], sh[c + 0]), 0.0f);
    o.y = fmaxf(fmaf(v.y, sc[c + 1], sh[c + 1]), 0.0f);
    o.z = fmaxf(fmaf(v.z, sc[c + 2], sh[c + 2]), 0.0f);
    o.w = fmaxf(fmaf(v.w, sc[c + 3], sh[c + 3]), 0.0f);
    *(uint2*)(g_A16 + (size_t)row * 256 + c) = pack_h16(o);
}

// ---------------- launch ----------------------------------------------------
extern "C" void kernel_launch(void* const* d_in, const int* in_sizes, int n_in,
                              void* d_out, int out_size) {
    const float* x   = (const float*)d_in[0];
    const void*  src = d_in[1];
    const void*  dst = d_in[2];
    const float* ws0 = (const float*)d_in[3];
    const float* wn0 = (const float*)d_in[4];
    const float* b0  = (const float*)d_in[5];
    const float* ws1 = (const float*)d_in[6];
    const float* wn1 = (const float*)d_in[7];
    const float* b1  = (const float*)d_in[8];
    const float* ws2 = (const float*)d_in[9];
    const float* wn2 = (const float*)d_in[10];
    const float* b2  = (const float*)d_in[11];
    const float* gamma0 = (const float*)d_in[12];
    const float* beta0  = (const float*)d_in[13];
    const float* gamma1 = (const float*)d_in[14];
    const float* beta1  = (const float*)d_in[15];
    float* out = (float*)d_out;

    void *hAp, *w16p;
    cudaGetSymbolAddress(&hAp, g_hA);
    cudaGetSymbolAddress(&w16p, g_W16);
    float* hA = (float*)hAp;
    const __half* w16 = (const __half*)w16p;

    const int SMEM128 = 2 * 16384 + 2 * 128 * 128;   // 65536
    const int SMEM64  = 2 * 16384 + 2 * 64 * 128;    // 49152
    cudaFuncSetAttribute(sage_mma<128, 0>, cudaFuncAttributeMaxDynamicSharedMemorySize, SMEM128);
    cudaFuncSetAttribute(sage_mma<64, 1>,  cudaFuncAttributeMaxDynamicSharedMemorySize, SMEM64);

    const int mgrid = (NN + 127) / 128;              // 782
    const int agrid = (NN * 32 + 255) / 256;         // 12500
    const int ngrid = (NN * 32 + 255) / 256;         // warp-per-node: 12500

    // 1: convert + scan-state reset + x/weight prep (disjoint block ranges)
    convert_prep_kernel<<<EGRID + XBLK + 320, 256>>>(
        src, dst, x, ws0, wn0, ws1, wn1, ws2, wn2);
    // 2: single-pass exclusive scan (decoupled lookback)
    scan_kernel<<<NBLK, 256>>>();
    // 3: CSR fill
    csr_fill_kernel<<<EGRID, 256>>>();

    // ---- layer 0 ----
    aggregate_kernel<<<ngrid, 256>>>();                                 // 4 <- profiled
    sage_mma<128, 0><<<mgrid, 256, SMEM128>>>(b0, hA, w16);             // 5
    bn_apply_kernel<<<agrid, 256>>>(gamma0, beta0, hA);                 // 6

    // ---- layer 1 ----
    aggregate_kernel<<<ngrid, 256>>>();                                 // 7
    sage_mma<128, 0><<<mgrid, 256, SMEM128>>>(b1, hA, w16 + 32768);     // 8
    bn_apply_kernel<<<agrid, 256>>>(gamma1, beta1, hA);                 // 9

    // ---- layer 2 (+ fused log_softmax) ----
    aggregate_kernel<<<ngrid, 256>>>();                                 // 10
    sage_mma<64, 1><<<mgrid, 256, SMEM64>>>(b2, out, w16 + 65536);      // 11
}

// round 15
// speedup vs baseline: 2.3401x; 1.0702x over previous
#include <cuda_runtime.h>
#include <cuda_fp16.h>
#include <math.h>
#include <stdint.h>

#define NN 100000
#define NE 1600000
#define HID 128
#define OUTF 64
#define NBLK ((NN + 255) / 256)   // 391 scan blocks
#define EGRID ((NE + 255) / 256)  // 6250 edge blocks
#define XBLK 12500                // NN*32/256 float4 chunks of x

// ---------------- scratch (static device globals; no allocations) ----------
__device__ int   g_src[NE];
__device__ int   g_dst[NE];
__device__ int   g_cnt[NN];
__device__ int   g_off[NN];
__device__ int   g_cur[NN];
__device__ int   g_csr[NE];
__device__ unsigned long long g_state[NBLK];   // decoupled-lookback scan state
__device__ int   g_ticket;
__device__ __align__(16) __half g_hA16[NN * HID];     // GEMM linear out (fp16)
__device__ __align__(16) __half g_A16[NN * 256];      // A = [h | agg] fp16
__device__ __align__(16) __half g_W16[320 * 256];     // W^T fp16, layers at 0/32768/65536
__device__ __align__(16) float g_bn[2][HID];          // [0]=sum [1]=sumsq

// ---------------- ptx helpers (all sm_80-era, no arch-'a' features) --------
__device__ __forceinline__ uint32_t smem_u32(const void* p) {
    uint32_t a;
    asm("{ .reg .u64 t; cvta.to.shared.u64 t, %1; cvt.u32.u64 %0, t; }"
        : "=r"(a) : "l"(p));
    return a;
}
__device__ __forceinline__ uint32_t sw128(uint32_t b) { return b ^ ((b >> 3) & 0x70); }

__device__ __forceinline__ void cp16(uint32_t sdst, const void* gsrc) {
    asm volatile("cp.async.cg.shared.global [%0], [%1], 16;"
                 :: "r"(sdst), "l"(gsrc) : "memory");
}
__device__ __forceinline__ void cp_commit() {
    asm volatile("cp.async.commit_group;" ::: "memory");
}
template<int W> __device__ __forceinline__ void cp_wait() {
    asm volatile("cp.async.wait_group %0;" :: "n"(W) : "memory");
}
__device__ __forceinline__ void ldm_x4(uint32_t* r, uint32_t a) {
    asm volatile("ldmatrix.sync.aligned.m8n8.x4.shared.b16 {%0,%1,%2,%3}, [%4];"
                 : "=r"(r[0]), "=r"(r[1]), "=r"(r[2]), "=r"(r[3]) : "r"(a));
}
__device__ __forceinline__ void ldm_x2(uint32_t* r, uint32_t a) {
    asm volatile("ldmatrix.sync.aligned.m8n8.x2.shared.b16 {%0,%1}, [%2];"
                 : "=r"(r[0]), "=r"(r[1]) : "r"(a));
}
__device__ __forceinline__ void mma_f16(float* d, const uint32_t* a, const uint32_t* b) {
    asm volatile("mma.sync.aligned.m16n8k16.row.col.f32.f16.f16.f32 "
                 "{%0,%1,%2,%3}, {%4,%5,%6,%7}, {%8,%9}, {%0,%1,%2,%3};"
                 : "+f"(d[0]), "+f"(d[1]), "+f"(d[2]), "+f"(d[3])
                 : "r"(a[0]), "r"(a[1]), "r"(a[2]), "r"(a[3]),
                   "r"(b[0]), "r"(b[1]));
}
__device__ __forceinline__ uint2 pack_h16(float4 v) {
    __half2 a = __floats2half2_rn(v.x, v.y);
    __half2 b = __floats2half2_rn(v.z, v.w);
    return make_uint2(*(uint32_t*)&a, *(uint32_t*)&b);
}

// ---------------- kernel 1: convert edges + scan-state reset + prep --------
// Blocks [0,EGRID): edge convert + degree count (+block 0 resets scan state).
// Blocks [EGRID, EGRID+XBLK): x -> fp16 into A cols 0..127.
// Blocks [EGRID+XBLK, +320): weight transpose -> fp16.
__global__ __launch_bounds__(256) void convert_prep_kernel(
    const void* srcv, const void* dstv, const float* __restrict__ x,
    const float* __restrict__ ws0, const float* __restrict__ wn0,
    const float* __restrict__ ws1, const float* __restrict__ wn1,
    const float* __restrict__ ws2, const float* __restrict__ wn2)
{
    int b = blockIdx.x;
    if (b < EGRID) {
        if (b == 0) {
            if (threadIdx.x == 0) g_ticket = 0;
            for (int j = threadIdx.x; j < NBLK; j += 256) g_state[j] = 0ull;
        }
        __shared__ int s_ok;
        const unsigned int* p = (const unsigned int*)srcv;
        if (threadIdx.x == 0) s_ok = 1;
        __syncthreads();
        if (threadIdx.x < 64) {
            // int64 with values < 2^31 -> all high words zero
            if (p[2 * threadIdx.x + 1] != 0u) s_ok = 0;
        }
        __syncthreads();
        int idx64 = s_ok;
        int e = b * 256 + threadIdx.x;
        if (e >= NE) return;
        int s, d;
        if (idx64) {
            s = (int)((const long long*)srcv)[e];
            d = (int)((const long long*)dstv)[e];
        } else {
            s = ((const int*)srcv)[e];
            d = ((const int*)dstv)[e];
        }
        g_src[e] = s;
        g_dst[e] = d;
        atomicAdd(&g_cnt[d], 1);
    } else if (b < EGRID + XBLK) {
        int idx = (b - EGRID) * 256 + threadIdx.x;   // float4 units over NN*128
        float4 v = ((const float4*)x)[idx];
        int row = idx >> 5;
        int c = (idx & 31) * 4;
        *(uint2*)(g_A16 + (size_t)row * 256 + c) = pack_h16(v);
    } else {
        int i = (b - EGRID - XBLK) * 256 + threadIdx.x;  // 0..81919
        const float *ws, *wn;
        int base, cols;
        if (i < 32768)      { ws = ws0; wn = wn0; base = 0;     cols = HID;  }
        else if (i < 65536) { ws = ws1; wn = wn1; base = 32768; cols = HID;  i -= 32768; }
        else                { ws = ws2; wn = wn2; base = 65536; cols = OUTF; i -= 65536; }
        int n = i >> 8;
        int k = i & 255;
        float v = (k < 128) ? ws[k * cols + n] : wn[(k - 128) * cols + n];
        g_W16[base + n * 256 + k] = __float2half_rn(v);
    }
}

// ---------------- kernel 2: single-pass scan (decoupled lookback) ----------
__global__ __launch_bounds__(256) void scan_kernel() {
    __shared__ int s[256];
    __shared__ int sbid, sprefix;
    if (threadIdx.x == 0) sbid = atomicAdd(&g_ticket, 1);
    __syncthreads();
    int bid = sbid;
    int i = bid * 256 + threadIdx.x;
    int v = (i < NN) ? g_cnt[i] : 0;
    if (i < NN) g_cnt[i] = 0;          // reset for next replay
    s[threadIdx.x] = v;
    __syncthreads();
#pragma unroll
    for (int off = 1; off < 256; off <<= 1) {
        int t = (threadIdx.x >= off) ? s[threadIdx.x - off] : 0;
        __syncthreads();
        s[threadIdx.x] += t;
        __syncthreads();
    }
    int total = s[255];
    if (threadIdx.x == 0) {
        if (bid == 0) {
            atomicExch(&g_state[0], (2ull << 32) | (unsigned)total);
            sprefix = 0;
        } else {
            atomicExch(&g_state[bid], (1ull << 32) | (unsigned)total);
            int prefix = 0;
            int j = bid - 1;
            while (true) {
                unsigned long long st = *(volatile unsigned long long*)&g_state[j];
                unsigned stat = (unsigned)(st >> 32);
                if (stat == 0u) continue;
                prefix += (int)(st & 0xffffffffu);
                if (stat == 2u) break;
                j--;
            }
            atomicExch(&g_state[bid], (2ull << 32) | (unsigned)(prefix + total));
            sprefix = prefix;
        }
    }
    __syncthreads();
    if (i < NN) {
        int o = sprefix + s[threadIdx.x] - v;   // global exclusive prefix
        g_off[i] = o;
        g_cur[i] = o;
    }
}

// ---------------- kernel 3: CSR fill ---------------------------------------
__global__ void csr_fill_kernel() {
    int e = blockIdx.x * blockDim.x + threadIdx.x;
    if (e >= NE) return;
    int pos = atomicAdd(&g_cur[g_dst[e]], 1);
    g_csr[pos] = g_src[e];
}

// ---------------- kernel 4: aggregation (profiled slot) --------------------
// CSR gather of fp16 rows (A cols 0..127), warp-per-node, 4 rows in flight.
// half2 pairwise-add tree (depth 2 in fp16) -> fp32 master accumulate.
// Mean, fp16 out to A cols 128..255. Block 0 zeroes BN accumulators.
__global__ __launch_bounds__(256) void aggregate_kernel() {
    if (blockIdx.x == 0 && threadIdx.x < 256)
        ((float*)g_bn)[threadIdx.x] = 0.0f;
    int node = (blockIdx.x * blockDim.x + threadIdx.x) >> 5;
    int lane = threadIdx.x & 31;
    if (node >= NN) return;
    int beg = g_off[node];
    int end = (node == NN - 1) ? NE : g_off[node + 1];
    float4 acc = make_float4(0.f, 0.f, 0.f, 0.f);
    int i = beg;
    for (; i + 4 <= end; i += 4) {
        int s0 = g_csr[i];
        int s1 = g_csr[i + 1];
        int s2 = g_csr[i + 2];
        int s3 = g_csr[i + 3];
        uint2 u0 = ((const uint2*)(g_A16 + (size_t)s0 * 256))[lane];
        uint2 u1 = ((const uint2*)(g_A16 + (size_t)s1 * 256))[lane];
        uint2 u2 = ((const uint2*)(g_A16 + (size_t)s2 * 256))[lane];
        uint2 u3 = ((const uint2*)(g_A16 + (size_t)s3 * 256))[lane];
        // fp16 pairwise tree: each element passes <=2 fp16 adds
        __half2 ax = __hadd2(*(__half2*)&u0.x, *(__half2*)&u1.x);
        __half2 bx = __hadd2(*(__half2*)&u2.x, *(__half2*)&u3.x);
        __half2 cx = __hadd2(ax, bx);
        __half2 ay = __hadd2(*(__half2*)&u0.y, *(__half2*)&u1.y);
        __half2 by = __hadd2(*(__half2*)&u2.y, *(__half2*)&u3.y);
        __half2 cy = __hadd2(ay, by);
        float2 fx = __half22float2(cx);
        float2 fy = __half22float2(cy);
        acc.x += fx.x; acc.y += fx.y; acc.z += fy.x; acc.w += fy.y;
    }
    for (; i < end; i++) {
        int s = g_csr[i];
        uint2 u = ((const uint2*)(g_A16 + (size_t)s * 256))[lane];
        float2 a = __half22float2(*(__half2*)&u.x);
        float2 b = __half22float2(*(__half2*)&u.y);
        acc.x += a.x; acc.y += a.y; acc.z += b.x; acc.w += b.y;
    }
    float r = 1.0f / (float)max(end - beg, 1);
    acc.x *= r; acc.y *= r; acc.z *= r; acc.w *= r;
    *(uint2*)(g_A16 + (size_t)node * 256 + 128 + lane * 4) = pack_h16(acc);
}

// ---------------- mma.sync GEMM: D = A(128x256) @ W^T, fp16 single-term ----
// Block 256 thr (8 warps), tile 128xCOLS, KC=64 (=128B row, SW128 atom),
// 4 stages double-buffered cp.async.
// Warp grid: COLS=128 -> 4Mx2N; COLS=64 -> 8Mx1N (log_softmax intra-warp).
// MODE 0: hA16 = fp16(D + bias), BN sum/sumsq accumulated into g_bn.
// MODE 1: out(fp32) = log_softmax(D + bias) rowwise.
template<int COLS, int MODE>
__global__ __launch_bounds__(256) void sage_mma(
    const float* __restrict__ bias, void* __restrict__ outp,
    const __half* __restrict__ w16)
{
    extern __shared__ __align__(1024) char smem[];
    constexpr int BB  = COLS * 128;          // B stage bytes
    constexpr int A1o = 16384;
    constexpr int B0o = 32768;
    constexpr int B1o = 32768 + BB;
    constexpr int NWN = (COLS == 128) ? 2 : 1;   // warps along N
    constexpr int NWM = 8 / NWN;                 // warps along M
    constexpr int MI  = 128 / (NWM * 16);        // m16 steps per warp (2 or 1)
    constexpr int WARP_N = COLS / NWN;           // 64
    constexpr int NI  = WARP_N / 8;              // 8

    const int tid  = threadIdx.x;
    const int wid  = tid >> 5;
    const int lane = tid & 31;
    const int wm   = wid / NWN;
    const int wn   = wid % NWN;
    const int row0 = blockIdx.x * 128;
    const uint32_t sb = smem_u32(smem);

    const int arow = wm * (MI * 16) + (lane & 15);   // + mi*16
    const int acb  = (lane >> 4) * 16;
    const int brow = wn * WARP_N + (lane & 7);       // + ni*8
    const int bcb  = ((lane >> 3) & 1) * 16;

    float acc[MI][NI][4];
#pragma unroll
    for (int mi = 0; mi < MI; mi++)
#pragma unroll
        for (int ni = 0; ni < NI; ni++)
#pragma unroll
            for (int q = 0; q < 4; q++) acc[mi][ni][q] = 0.0f;

    auto load_stage = [&](int ks, int buf) {
        uint32_t Ab = sb + (buf ? A1o : 0);
        uint32_t Bb = sb + (buf ? B1o : B0o);
#pragma unroll
        for (int i = 0; i < 4; i++) {                // A: 128 rows x 8 chunks
            int u = tid + i * 256;
            int r = u >> 3, c = u & 7;
            int rowg = min(row0 + r, NN - 1);
            cp16(Ab + sw128(r * 128 + c * 16),
                 g_A16 + (size_t)rowg * 256 + ks * 64 + c * 8);
        }
#pragma unroll
        for (int i = 0; i < COLS / 32; i++) {        // B: COLS x 8 chunks
            int u = tid + i * 256;
            int n = u >> 3, c = u & 7;
            cp16(Bb + sw128(n * 128 + c * 16),
                 w16 + (size_t)n * 256 + ks * 64 + c * 8);
        }
    };

    auto compute_stage = [&](int buf) {
        uint32_t Ab = sb + (buf ? A1o : 0);
        uint32_t Bb = sb + (buf ? B1o : B0o);
#pragma unroll
        for (int kk = 0; kk < 4; kk++) {             // four k16 steps per stage
            uint32_t bf[NI][2];
#pragma unroll
            for (int ni = 0; ni < NI; ni++) {
                uint32_t off = (uint32_t)(brow + ni * 8) * 128 + kk * 32 + bcb;
                ldm_x2(bf[ni], Bb + sw128(off));
            }
#pragma unroll
            for (int mi = 0; mi < MI; mi++) {
                uint32_t af[4];
                uint32_t off = (uint32_t)(arow + mi * 16) * 128 + kk * 32 + acb;
                ldm_x4(af, Ab + sw128(off));
#pragma unroll
                for (int ni = 0; ni < NI; ni++)
                    mma_f16(acc[mi][ni], af, bf[ni]);
            }
        }
    };

    load_stage(0, 0);
    cp_commit();
    for (int ks = 0; ks < 4; ks++) {
        if (ks < 3) {
            load_stage(ks + 1, (ks + 1) & 1);
            cp_commit();
            cp_wait<1>();
        } else {
            cp_wait<0>();
        }
        __syncthreads();
        compute_stage(ks & 1);
        __syncthreads();
    }

    // ---- epilogue: add bias into acc ----
#pragma unroll
    for (int mi = 0; mi < MI; mi++)
#pragma unroll
        for (int ni = 0; ni < NI; ni++) {
            int c = wn * WARP_N + ni * 8 + (lane & 3) * 2;
            float b0 = __ldg(bias + c), b1 = __ldg(bias + c + 1);
            acc[mi][ni][0] += b0; acc[mi][ni][1] += b1;
            acc[mi][ni][2] += b0; acc[mi][ni][3] += b1;
        }

    const int r_base = row0 + wm * (MI * 16) + (lane >> 2);

    if (MODE == 0) {
        __half* outh = (__half*)outp;
        // store fp16 + per-thread BN partials in fp32 (row-guarded)
        float vs[2 * NI], vq[2 * NI];
#pragma unroll
        for (int j = 0; j < 2 * NI; j++) { vs[j] = 0.f; vq[j] = 0.f; }
#pragma unroll
        for (int mi = 0; mi < MI; mi++) {
            int rA = r_base + mi * 16;
            int rB = rA + 8;
            bool gA = rA < NN, gB = rB < NN;
#pragma unroll
            for (int ni = 0; ni < NI; ni++) {
                int c = wn * WARP_N + ni * 8 + (lane & 3) * 2;
                if (gA) {
                    float ox = acc[mi][ni][0], oy = acc[mi][ni][1];
                    __half2 h = __floats2half2_rn(ox, oy);
                    *(uint32_t*)(outh + (size_t)rA * COLS + c) = *(uint32_t*)&h;
                    vs[2 * ni] += ox;     vq[2 * ni] += ox * ox;
                    vs[2 * ni + 1] += oy; vq[2 * ni + 1] += oy * oy;
                }
                if (gB) {
                    float ox = acc[mi][ni][2], oy = acc[mi][ni][3];
                    __half2 h = __floats2half2_rn(ox, oy);
                    *(uint32_t*)(outh + (size_t)rB * COLS + c) = *(uint32_t*)&h;
                    vs[2 * ni] += ox;     vq[2 * ni] += ox * ox;
                    vs[2 * ni + 1] += oy; vq[2 * ni + 1] += oy * oy;
                }
            }
        }
        // block reduce in smem (stage buffers are dead now), then global atomics
        float* sred = (float*)smem;      // [0..127]=sum, [128..255]=sumsq
        sred[tid] = 0.0f;
        __syncthreads();
#pragma unroll
        for (int ni = 0; ni < NI; ni++) {
            int c = wn * WARP_N + ni * 8 + (lane & 3) * 2;
            atomicAdd(&sred[c],           vs[2 * ni]);
            atomicAdd(&sred[c + 1],       vs[2 * ni + 1]);
            atomicAdd(&sred[128 + c],     vq[2 * ni]);
            atomicAdd(&sred[128 + c + 1], vq[2 * ni + 1]);
        }
        __syncthreads();
        if (tid < 256) atomicAdd(&((float*)g_bn)[tid], sred[tid]);
    } else {
        float* outf = (float*)outp;
        // log_softmax over COLS=64: one warp owns all 64 cols of its rows.
#pragma unroll
        for (int mi = 0; mi < MI; mi++) {
            float mA = -INFINITY, mB = -INFINITY;
#pragma unroll
            for (int ni = 0; ni < NI; ni++) {
                mA = fmaxf(mA, fmaxf(acc[mi][ni][0], acc[mi][ni][1]));
                mB = fmaxf(mB, fmaxf(acc[mi][ni][2], acc[mi][ni][3]));
            }
#pragma unroll
            for (int off = 1; off <= 2; off <<= 1) {
                mA = fmaxf(mA, __shfl_xor_sync(0xffffffffu, mA, off));
                mB = fmaxf(mB, __shfl_xor_sync(0xffffffffu, mB, off));
            }
            float sA = 0.f, sB = 0.f;
#pragma unroll
            for (int ni = 0; ni < NI; ni++) {
                sA += expf(acc[mi][ni][0] - mA) + expf(acc[mi][ni][1] - mA);
                sB += expf(acc[mi][ni][2] - mB) + expf(acc[mi][ni][3] - mB);
            }
#pragma unroll
            for (int off = 1; off <= 2; off <<= 1) {
                sA += __shfl_xor_sync(0xffffffffu, sA, off);
                sB += __shfl_xor_sync(0xffffffffu, sB, off);
            }
            float lseA = mA + logf(sA);
            float lseB = mB + logf(sB);
            int rA = r_base + mi * 16;
            int rB = rA + 8;
#pragma unroll
            for (int ni = 0; ni < NI; ni++) {
                int c = wn * WARP_N + ni * 8 + (lane & 3) * 2;
                if (rA < NN) {
                    float2 o = make_float2(acc[mi][ni][0] - lseA, acc[mi][ni][1] - lseA);
                    *(float2*)(outf + (size_t)rA * COLS + c) = o;
                }
                if (rB < NN) {
                    float2 o = make_float2(acc[mi][ni][2] - lseB, acc[mi][ni][3] - lseB);
                    *(float2*)(outf + (size_t)rB * COLS + c) = o;
                }
            }
        }
    }
}

// ---------------- BN finalize (inline) + apply + ReLU -> fp16 A cols 0..127
__global__ __launch_bounds__(256) void bn_apply_kernel(
    const float* __restrict__ gamma, const float* __restrict__ beta)
{
    __shared__ float sc[HID], sh[HID];
    if (threadIdx.x < HID) {
        int c = threadIdx.x;
        float s  = g_bn[0][c];
        float sq = g_bn[1][c];
        float mu  = s / (float)NN;
        float var = sq / (float)NN - mu * mu;
        float scv = gamma[c] * rsqrtf(var + 1e-5f);
        sc[c] = scv;
        sh[c] = beta[c] - mu * scv;
    }
    __syncthreads();
    int idx = blockIdx.x * blockDim.x + threadIdx.x;   // 4-col units
    if (idx >= NN * 32) return;
    int row = idx >> 5;
    int c = (idx & 31) * 4;
    uint2 u = *(const uint2*)(g_hA16 + (size_t)row * HID + c);
    float2 v01 = __half22float2(*(__half2*)&u.x);
    float2 v23 = __half22float2(*(__half2*)&u.y);
    float4 o;
    o.x = fmaxf(fmaf(v01.x, sc[c + 0], sh[c + 0]), 0.0f);
    o.y = fmaxf(fmaf(v01.y, sc[c + 1], sh[c + 1]), 0.0f);
    o.z = fmaxf(fmaf(v23.x, sc[c + 2], sh[c + 2]), 0.0f);
    o.w = fmaxf(fmaf(v23.y, sc[c + 3], sh[c + 3]), 0.0f);
    *(uint2*)(g_A16 + (size_t)row * 256 + c) = pack_h16(o);
}

// ---------------- launch ----------------------------------------------------
extern "C" void kernel_launch(void* const* d_in, const int* in_sizes, int n_in,
                              void* d_out, int out_size) {
    const float* x   = (const float*)d_in[0];
    const void*  src = d_in[1];
    const void*  dst = d_in[2];
    const float* ws0 = (const float*)d_in[3];
    const float* wn0 = (const float*)d_in[4];
    const float* b0  = (const float*)d_in[5];
    const float* ws1 = (const float*)d_in[6];
    const float* wn1 = (const float*)d_in[7];
    const float* b1  = (const float*)d_in[8];
    const float* ws2 = (const float*)d_in[9];
    const float* wn2 = (const float*)d_in[10];
    const float* b2  = (const float*)d_in[11];
    const float* gamma0 = (const float*)d_in[12];
    const float* beta0  = (const float*)d_in[13];
    const float* gamma1 = (const float*)d_in[14];
    const float* beta1  = (const float*)d_in[15];
    float* out = (float*)d_out;

    void *hAp, *w16p;
    cudaGetSymbolAddress(&hAp, g_hA16);
    cudaGetSymbolAddress(&w16p, g_W16);
    __half* hA16 = (__half*)hAp;
    const __half* w16 = (const __half*)w16p;

    const int SMEM128 = 2 * 16384 + 2 * 128 * 128;   // 65536
    const int SMEM64  = 2 * 16384 + 2 * 64 * 128;    // 49152
    cudaFuncSetAttribute(sage_mma<128, 0>, cudaFuncAttributeMaxDynamicSharedMemorySize, SMEM128);
    cudaFuncSetAttribute(sage_mma<64, 1>,  cudaFuncAttributeMaxDynamicSharedMemorySize, SMEM64);

    const int mgrid = (NN + 127) / 128;              // 782
    const int agrid = (NN * 32 + 255) / 256;         // 12500
    const int ngrid = (NN * 32 + 255) / 256;         // warp-per-node: 12500

    // 1: convert + scan-state reset + x/weight prep (disjoint block ranges)
    convert_prep_kernel<<<EGRID + XBLK + 320, 256>>>(
        src, dst, x, ws0, wn0, ws1, wn1, ws2, wn2);
    // 2: single-pass exclusive scan (decoupled lookback)
    scan_kernel<<<NBLK, 256>>>();
    // 3: CSR fill
    csr_fill_kernel<<<EGRID, 256>>>();

    // ---- layer 0 ----
    aggregate_kernel<<<ngrid, 256>>>();                                 // 4 <- profiled
    sage_mma<128, 0><<<mgrid, 256, SMEM128>>>(b0, hA16, w16);           // 5
    bn_apply_kernel<<<agrid, 256>>>(gamma0, beta0);                     // 6

    // ---- layer 1 ----
    aggregate_kernel<<<ngrid, 256>>>();                                 // 7
    sage_mma<128, 0><<<mgrid, 256, SMEM128>>>(b1, hA16, w16 + 32768);   // 8
    bn_apply_kernel<<<agrid, 256>>>(gamma1, beta1);                     // 9

    // ---- layer 2 (+ fused log_softmax) ----
    aggregate_kernel<<<ngrid, 256>>>();                                 // 10
    sage_mma<64, 1><<<mgrid, 256, SMEM64>>>(b2, out, w16 + 65536);      // 11
}